// round 1
// baseline (speedup 1.0000x reference)
#include <cuda_runtime.h>
#include <cuda_bf16.h>
#include <math.h>

// ---------------- problem constants ----------------
#define BATCH   256
#define FRAMES  4
#define LTOK    20            // tokens per frame
#define NTOK    81            // 1 + FRAMES*LTOK
#define EMBED   768
#define HEADS   12
#define HDIM    64
#define DEPTH   12
#define FEAT    2048
#define XROW    2054
#define M_ALL   (BATCH * NTOK)        // 20736
#define M_SPAT  (BATCH * FRAMES * LTOK) // 20480
#define OUTD    256

// ---------------- scratch (device globals; no allocation allowed) ----------------
__device__ float g_X[M_ALL * EMBED];        // residual stream
__device__ float g_Y[M_ALL * EMBED];        // LN output / attention output
__device__ float g_S[M_ALL * 4 * EMBED];    // qkv (2304) / mlp hidden (3072) / embed tmp
__device__ float g_MB[M_ALL];               // mbias

// ---------------- generic SGEMM: C = act(A @ W^T + bias) (+= optional) ----------------
// A: (M,K) row-major stride lda ; W: (N,K) row-major stride ldw ; C: (M,N) stride ldc
// Block tile 128x128, K-step 8, 256 threads, 8x8 per-thread microtile.
// All M,N,K used here are multiples of 128/128/8 -> no bounds checks.
#define BM 128
#define BN 128
#define BKK 8

__device__ __forceinline__ float gelu_exact(float x) {
    return 0.5f * x * (1.0f + erff(x * 0.70710678118654752f));
}

template<int ACT, int ACC>
__global__ void __launch_bounds__(256) gemm_k(
    const float* __restrict__ A, int lda,
    const float* __restrict__ W, int ldw,
    const float* __restrict__ bias,
    float* __restrict__ C, int ldc, int K)
{
    __shared__ float As[BKK][BM];
    __shared__ float Bs[BKK][BN];

    const int tid = threadIdx.x;
    const int tx  = tid & 15;          // 0..15 -> N dim
    const int ty  = tid >> 4;          // 0..15 -> M dim
    const int row0 = blockIdx.y * BM;
    const int col0 = blockIdx.x * BN;

    const int ldr = tid >> 1;          // 0..127 load row
    const int kb  = (tid & 1) * 4;     // 0 or 4

    const float* Ab = A + (long)(row0 + ldr) * lda + kb;
    const float* Wb = W + (long)(col0 + ldr) * ldw + kb;

    float acc[8][8];
    #pragma unroll
    for (int i = 0; i < 8; i++)
        #pragma unroll
        for (int j = 0; j < 8; j++) acc[i][j] = 0.0f;

    for (int k0 = 0; k0 < K; k0 += BKK) {
        #pragma unroll
        for (int j = 0; j < 4; j++) As[kb + j][ldr] = Ab[k0 + j];
        #pragma unroll
        for (int j = 0; j < 4; j++) Bs[kb + j][ldr] = Wb[k0 + j];
        __syncthreads();
        #pragma unroll
        for (int k = 0; k < BKK; k++) {
            float a[8], b[8];
            *(float4*)&a[0] = *(const float4*)&As[k][ty * 8];
            *(float4*)&a[4] = *(const float4*)&As[k][ty * 8 + 4];
            *(float4*)&b[0] = *(const float4*)&Bs[k][tx * 8];
            *(float4*)&b[4] = *(const float4*)&Bs[k][tx * 8 + 4];
            #pragma unroll
            for (int i = 0; i < 8; i++)
                #pragma unroll
                for (int j = 0; j < 8; j++)
                    acc[i][j] = fmaf(a[i], b[j], acc[i][j]);
        }
        __syncthreads();
    }

    #pragma unroll
    for (int i = 0; i < 8; i++) {
        const long row = row0 + ty * 8 + i;
        float* crow = C + row * (long)ldc + col0 + tx * 8;
        #pragma unroll
        for (int j = 0; j < 8; j++) {
            float v = acc[i][j];
            if (bias) v += bias[col0 + tx * 8 + j];
            if (ACT == 1) v = gelu_exact(v);
            if (ACC) crow[j] += v;
            else     crow[j]  = v;
        }
    }
}

// ---------------- LayerNorm: one block per token ----------------
__global__ void __launch_bounds__(256) ln_k(
    const float* __restrict__ X, const float* __restrict__ w,
    const float* __restrict__ b, float* __restrict__ Y)
{
    const long t = blockIdx.x;
    const float* xr = X + t * EMBED;
    float*       yr = Y + t * EMBED;
    const int tid = threadIdx.x;

    float v0 = xr[tid], v1 = xr[tid + 256], v2 = xr[tid + 512];
    float s  = v0 + v1 + v2;
    float ss = v0 * v0 + v1 * v1 + v2 * v2;

    __shared__ float red[64];
    // warp reduce
    for (int o = 16; o; o >>= 1) {
        s  += __shfl_xor_sync(0xffffffffu, s,  o);
        ss += __shfl_xor_sync(0xffffffffu, ss, o);
    }
    const int warp = tid >> 5, lane = tid & 31;
    if (lane == 0) { red[warp] = s; red[warp + 8] = ss; }
    __syncthreads();
    __shared__ float smean, srstd;
    if (tid == 0) {
        float S = 0, SS = 0;
        #pragma unroll
        for (int i = 0; i < 8; i++) { S += red[i]; SS += red[i + 8]; }
        float m  = S * (1.0f / EMBED);
        float var = SS * (1.0f / EMBED) - m * m;
        smean = m;
        srstd = rsqrtf(var + 1e-6f);
    }
    __syncthreads();
    const float m = smean, r = srstd;
    yr[tid]       = (v0 - m) * r * w[tid]       + b[tid];
    yr[tid + 256] = (v1 - m) * r * w[tid + 256] + b[tid + 256];
    yr[tid + 512] = (v2 - m) * r * w[tid + 512] + b[tid + 512];
}

// ---------------- variant attention: one block per (batch, head) ----------------
// QKV layout per token: [q(768) k(768) v(768)]; head hh uses cols hh*64..+64.
// cls query (i=0) attends to all 81 keys; spatial query i (frame f) attends to
// {cls} + 20 frame tokens. Additive bias mbs[tok] everywhere.
__global__ void __launch_bounds__(256) attn_k(
    const float* __restrict__ QKV, const float* __restrict__ MB,
    float* __restrict__ O)
{
    extern __shared__ float sm[];
    float* Qs = sm;                 // 81*64
    float* Ks = sm + NTOK * HDIM;   // 81*64
    float* Vs = sm + 2 * NTOK * HDIM;
    __shared__ float probs[8][NTOK];
    __shared__ float mbs[NTOK];

    const int bh = blockIdx.x;
    const int b  = bh / HEADS, hh = bh % HEADS;
    const float* base = QKV + (long)b * NTOK * (3 * EMBED) + hh * HDIM;

    for (int idx = threadIdx.x; idx < NTOK * HDIM; idx += 256) {
        const int i = idx >> 6, c = idx & 63;
        const float* p = base + (long)i * (3 * EMBED) + c;
        Qs[idx] = p[0] * 0.125f;   // d^-0.5
        Ks[idx] = p[EMBED];
        Vs[idx] = p[2 * EMBED];
    }
    if (threadIdx.x < NTOK) mbs[threadIdx.x] = MB[b * NTOK + threadIdx.x];
    __syncthreads();

    const int warp = threadIdx.x >> 5, lane = threadIdx.x & 31;

    for (int i = warp; i < NTOK; i += 8) {
        int nk, fbase = 0;
        if (i == 0) nk = NTOK;
        else { const int f = (i - 1) / LTOK; fbase = 1 + f * LTOK; nk = LTOK + 1; }

        float sims[3];
        float mx = -1e30f;
        int s = 0;
        for (int t = lane; t < nk; t += 32, s++) {
            const int tok = (i == 0) ? t : (t == 0 ? 0 : fbase + t - 1);
            const float* kk = Ks + tok * HDIM;
            const float* qq = Qs + i * HDIM;
            float d = 0.0f;
            #pragma unroll
            for (int c = 0; c < HDIM; c++) d = fmaf(qq[c], kk[c], d);
            sims[s] = d + mbs[tok];
            mx = fmaxf(mx, sims[s]);
        }
        for (int o = 16; o; o >>= 1) mx = fmaxf(mx, __shfl_xor_sync(0xffffffffu, mx, o));
        float lsum = 0.0f;
        s = 0;
        for (int t = lane; t < nk; t += 32, s++) {
            const float p = expf(sims[s] - mx);
            probs[warp][t] = p;
            lsum += p;
        }
        for (int o = 16; o; o >>= 1) lsum += __shfl_xor_sync(0xffffffffu, lsum, o);
        const float inv = 1.0f / lsum;
        __syncwarp();

        float o0 = 0.0f, o1 = 0.0f;
        const int c0 = lane * 2;
        for (int t = 0; t < nk; t++) {
            const int tok = (i == 0) ? t : (t == 0 ? 0 : fbase + t - 1);
            const float p = probs[warp][t];
            o0 = fmaf(p, Vs[tok * HDIM + c0],     o0);
            o1 = fmaf(p, Vs[tok * HDIM + c0 + 1], o1);
        }
        float* op = O + ((long)(b * NTOK + i)) * EMBED + hh * HDIM + c0;
        op[0] = o0 * inv;
        op[1] = o1 * inv;
        __syncwarp();
    }
}

// ---------------- embed epilogue: pos features, biases, temporal embed, mask ----------------
__global__ void __launch_bounds__(256) embed_finish_k(
    const float* __restrict__ S, const float* __restrict__ x,
    const float* __restrict__ objb, const float* __restrict__ posb,
    const float* __restrict__ posW, const float* __restrict__ te,
    const int* __restrict__ xmask, float* __restrict__ X, float* __restrict__ MB)
{
    const int t = blockIdx.x;                  // 0..20479
    const int b = t / (FRAMES * LTOK);
    const int j = t % (FRAMES * LTOK);
    const int f = j / LTOK;

    __shared__ float xp[6];
    if (threadIdx.x < 6) xp[threadIdx.x] = x[(long)t * XROW + FEAT + threadIdx.x];
    __syncthreads();

    const long orow = ((long)b * NTOK + 1 + j) * EMBED;
    for (int e = threadIdx.x; e < EMBED; e += 256) {
        float v = S[(long)t * EMBED + e] + objb[e] + posb[e] + te[f * EMBED + e];
        #pragma unroll
        for (int k = 0; k < 6; k++) v = fmaf(xp[k], posW[e * 6 + k], v);
        X[orow + e] = v;
    }
    if (threadIdx.x == 0) MB[b * NTOK + 1 + j] = xmask[t] ? 0.0f : -100.0f;
}

__global__ void __launch_bounds__(256) cls_init_k(
    const float* __restrict__ cls_tok, const float* __restrict__ cls_pos,
    float* __restrict__ X, float* __restrict__ MB)
{
    const int b = blockIdx.x;
    for (int e = threadIdx.x; e < EMBED; e += 256)
        X[(long)b * NTOK * EMBED + e] = cls_tok[e] + cls_pos[e];
    if (threadIdx.x == 0) MB[b * NTOK] = 0.0f;
}

__global__ void __launch_bounds__(256) copy_mbias_k(
    const float* __restrict__ MB, float* __restrict__ out)
{
    const int i = blockIdx.x * 256 + threadIdx.x;
    if (i < M_ALL) out[i] = MB[i];
}

// ---------------- host orchestration ----------------
extern "C" void kernel_launch(void* const* d_in, const int* in_sizes, int n_in,
                              void* d_out, int out_size)
{
    const float* x        = (const float*)d_in[0];
    const int*   x_mask   = (const int*)  d_in[1];
    const float* obj_W    = (const float*)d_in[2];
    const float* obj_b    = (const float*)d_in[3];
    const float* pos_W    = (const float*)d_in[4];
    const float* pos_b    = (const float*)d_in[5];
    const float* cls_tok  = (const float*)d_in[6];
    const float* cls_pos  = (const float*)d_in[7];
    const float* temporal = (const float*)d_in[8];
    const float* ln1_w    = (const float*)d_in[9];
    const float* ln1_b    = (const float*)d_in[10];
    const float* ln2_w    = (const float*)d_in[11];
    const float* ln2_b    = (const float*)d_in[12];
    const float* qkv_W    = (const float*)d_in[13];
    const float* qkv_b    = (const float*)d_in[14];
    const float* ap_W     = (const float*)d_in[15];
    const float* ap_b     = (const float*)d_in[16];
    const float* fc1_W    = (const float*)d_in[17];
    const float* fc1_b    = (const float*)d_in[18];
    const float* fc2_W    = (const float*)d_in[19];
    const float* fc2_b    = (const float*)d_in[20];
    const float* proj_W   = (const float*)d_in[21];

    float *gX, *gY, *gS, *gM;
    cudaGetSymbolAddress((void**)&gX, g_X);
    cudaGetSymbolAddress((void**)&gY, g_Y);
    cudaGetSymbolAddress((void**)&gS, g_S);
    cudaGetSymbolAddress((void**)&gM, g_MB);

    const int attn_smem = 3 * NTOK * HDIM * (int)sizeof(float);   // 62208 B
    cudaFuncSetAttribute(attn_k, cudaFuncAttributeMaxDynamicSharedMemorySize, attn_smem);

    // ---- embedding ----
    // g_S[0:20480*768] = x[:, :2048] @ obj_W^T
    gemm_k<0,0><<<dim3(EMBED / BN, M_SPAT / BM), 256>>>(
        x, XROW, obj_W, FEAT, nullptr, gS, EMBED, FEAT);
    embed_finish_k<<<M_SPAT, 256>>>(gS, x, obj_b, pos_b, pos_W, temporal, x_mask, gX, gM);
    cls_init_k<<<BATCH, 256>>>(cls_tok, cls_pos, gX, gM);

    // ---- transformer layers ----
    for (int l = 0; l < DEPTH; l++) {
        const float* qW  = qkv_W + (long)l * 3 * EMBED * EMBED;
        const float* qb  = qkv_b + (long)l * 3 * EMBED;
        const float* aW  = ap_W  + (long)l * EMBED * EMBED;
        const float* ab  = ap_b  + (long)l * EMBED;
        const float* f1W = fc1_W + (long)l * 4 * EMBED * EMBED;
        const float* f1b = fc1_b + (long)l * 4 * EMBED;
        const float* f2W = fc2_W + (long)l * EMBED * 4 * EMBED;
        const float* f2b = fc2_b + (long)l * EMBED;

        // Y = LN1(X)
        ln_k<<<M_ALL, 256>>>(gX, ln1_w + l * EMBED, ln1_b + l * EMBED, gY);
        // S = Y @ qkvW^T + qkvb        (M_ALL x 2304)
        gemm_k<0,0><<<dim3(3 * EMBED / BN, M_ALL / BM), 256>>>(
            gY, EMBED, qW, EMBED, qb, gS, 3 * EMBED, EMBED);
        // Y = attention(S, mbias)
        attn_k<<<BATCH * HEADS, 256, attn_smem>>>(gS, gM, gY);
        // X += Y @ apW^T + apb
        gemm_k<0,1><<<dim3(EMBED / BN, M_ALL / BM), 256>>>(
            gY, EMBED, aW, EMBED, ab, gX, EMBED, EMBED);
        // Y = LN2(X)
        ln_k<<<M_ALL, 256>>>(gX, ln2_w + l * EMBED, ln2_b + l * EMBED, gY);
        // S = gelu(Y @ fc1W^T + fc1b)  (M_ALL x 3072)
        gemm_k<1,0><<<dim3(4 * EMBED / BN, M_ALL / BM), 256>>>(
            gY, EMBED, f1W, EMBED, f1b, gS, 4 * EMBED, EMBED);
        // X += S @ fc2W^T + fc2b
        gemm_k<0,1><<<dim3(EMBED / BN, M_ALL / BM), 256>>>(
            gS, 4 * EMBED, f2W, 4 * EMBED, f2b, gX, EMBED, 4 * EMBED);
    }

    // ---- head: out1 = X @ proj_W^T  (M_ALL x 256), then mbias appended ----
    float* out = (float*)d_out;
    gemm_k<0,0><<<dim3(OUTD / BN, M_ALL / BM), 256>>>(
        gX, EMBED, proj_W, EMBED, nullptr, out, OUTD, EMBED);

    if (out_size >= M_ALL * OUTD + M_ALL) {
        copy_mbias_k<<<(M_ALL + 255) / 256, 256>>>(gM, out + (long)M_ALL * OUTD);
    }
}

// round 4
// speedup vs baseline: 4.1553x; 4.1553x over previous
#include <cuda_runtime.h>
#include <cuda_bf16.h>
#include <math.h>
#include <stdint.h>

// ---------------- problem constants ----------------
#define BATCH   256
#define FRAMES  4
#define LTOK    20
#define NTOK    81
#define EMBED   768
#define HEADS   12
#define HDIM    64
#define DEPTH   12
#define FEAT    2048
#define XROW    2054
#define M_ALL   (BATCH * NTOK)          // 20736
#define M_SPAT  (BATCH * FRAMES * LTOK) // 20480
#define OUTD    256

// weight offsets (elements) in the packed bf16 weight buffers
#define OFF_OBJ  0L
#define OFF_QKV  1572864L
#define OFF_AP   22806528L
#define OFF_FC1  29884416L
#define OFF_FC2  58195968L
#define OFF_PROJ 86507520L
#define W_TOTAL  86704128L

// ---------------- scratch ----------------
__device__ float g_X[M_ALL * EMBED];
__device__ float g_S[M_ALL * 4 * EMBED];
__device__ float g_MB[M_ALL];
__device__ __nv_bfloat16 g_Ah[63700992];          // M_ALL*3072 (embed input / fc1 out)
__device__ __nv_bfloat16 g_Al[63700992];
__device__ __nv_bfloat16 g_Bh[M_ALL * EMBED];     // 768-wide activations
__device__ __nv_bfloat16 g_Bl[M_ALL * EMBED];
__device__ __nv_bfloat16 g_Wh[W_TOTAL];
__device__ __nv_bfloat16 g_Wl[W_TOTAL];

// ---------------- helpers ----------------
__device__ __forceinline__ uint32_t smem_u32(const void* p) {
    uint32_t a;
    asm("{ .reg .u64 t; cvta.to.shared.u64 t, %1; cvt.u32.u64 %0, t; }" : "=r"(a) : "l"(p));
    return a;
}
__device__ __forceinline__ void cpa16(uint32_t dst, const void* src) {
    asm volatile("cp.async.cg.shared.global [%0], [%1], 16;" :: "r"(dst), "l"(src));
}
__device__ __forceinline__ void ldsm4(uint32_t* r, uint32_t addr) {
    asm volatile("ldmatrix.sync.aligned.m8n8.x4.shared.b16 {%0,%1,%2,%3}, [%4];"
                 : "=r"(r[0]), "=r"(r[1]), "=r"(r[2]), "=r"(r[3]) : "r"(addr));
}
__device__ __forceinline__ void mma16816(float* c, const uint32_t* a, const uint32_t* b) {
    asm volatile(
        "mma.sync.aligned.m16n8k16.row.col.f32.bf16.bf16.f32 "
        "{%0,%1,%2,%3}, {%4,%5,%6,%7}, {%8,%9}, {%0,%1,%2,%3};"
        : "+f"(c[0]), "+f"(c[1]), "+f"(c[2]), "+f"(c[3])
        : "r"(a[0]), "r"(a[1]), "r"(a[2]), "r"(a[3]), "r"(b[0]), "r"(b[1]));
}
__device__ __forceinline__ float gelu_exact(float x) {
    return 0.5f * x * (1.0f + erff(x * 0.70710678118654752f));
}
__device__ __forceinline__ void split2(float v, __nv_bfloat16& h, __nv_bfloat16& l) {
    h = __float2bfloat16(v);
    l = __float2bfloat16(v - __bfloat162float(h));
}

// ---------------- bf16 hi/lo split GEMM on mma.sync ----------------
#define KC 64
#define STAGE_BYTES 65536  // 4 buffers x 16KB (Ah Al Bh Bl), chunk 128x64 bf16 each

template<int ACT, int ACC, int OSPLIT>
__global__ void __launch_bounds__(256, 1) gemm_mma(
    const __nv_bfloat16* __restrict__ Ah, const __nv_bfloat16* __restrict__ Al, int lda,
    const __nv_bfloat16* __restrict__ Bh, const __nv_bfloat16* __restrict__ Bl, int ldw,
    const float* __restrict__ bias,
    float* __restrict__ C,
    __nv_bfloat16* __restrict__ Oh, __nv_bfloat16* __restrict__ Ol,
    int ldc, int K)
{
    extern __shared__ char smem[];
    const uint32_t sbase = smem_u32(smem);
    const int tid = threadIdx.x, wid = tid >> 5, lane = tid & 31;
    const int row0 = blockIdx.y * 128, col0 = blockIdx.x * 128;
    const int warp_m = (wid & 1) * 64, warp_n = (wid >> 1) * 32;

    const __nv_bfloat16* g0 = Ah + (long)row0 * lda;
    const __nv_bfloat16* g1 = Al + (long)row0 * lda;
    const __nv_bfloat16* g2 = Bh + (long)col0 * ldw;
    const __nv_bfloat16* g3 = Bl + (long)col0 * ldw;

    float acc[4][4][4];
    #pragma unroll
    for (int a = 0; a < 4; a++)
        #pragma unroll
        for (int b = 0; b < 4; b++)
            #pragma unroll
            for (int c = 0; c < 4; c++) acc[a][b][c] = 0.0f;

    const int id  = lane >> 3;
    const int rin = lane & 7;
    const int a_row = warp_m + ((id & 1) << 3) + rin;
    const int b_row = warp_n + ((id >> 1) << 3) + rin;
    const int ag = id >> 1;
    const int bg = id & 1;

    const int nk = K / KC;

#define LOAD_STAGE(stage, k0)                                                        \
    {                                                                                \
        const uint32_t st_ = sbase + (stage) * STAGE_BYTES;                          \
        _Pragma("unroll")                                                            \
        for (int i = 0; i < 4; i++) {                                                \
            const int c_ = tid + i * 256;                                            \
            const int row_ = c_ >> 3, gg_ = c_ & 7;                                  \
            const uint32_t ph_ = row_ * 128 + ((gg_ ^ (row_ & 7)) << 4);             \
            cpa16(st_ + ph_,          g0 + (long)row_ * lda + (k0) + gg_ * 8);       \
            cpa16(st_ + 16384 + ph_,  g1 + (long)row_ * lda + (k0) + gg_ * 8);       \
            cpa16(st_ + 32768 + ph_,  g2 + (long)row_ * ldw + (k0) + gg_ * 8);       \
            cpa16(st_ + 49152 + ph_,  g3 + (long)row_ * ldw + (k0) + gg_ * 8);       \
        }                                                                            \
        asm volatile("cp.async.commit_group;" ::: "memory");                         \
    }

    LOAD_STAGE(0, 0);

    for (int ck = 0; ck < nk; ck++) {
        const int s = ck & 1;
        if (ck + 1 < nk) {
            LOAD_STAGE(s ^ 1, (ck + 1) * KC);
            asm volatile("cp.async.wait_group 1;" ::: "memory");
        } else {
            asm volatile("cp.async.wait_group 0;" ::: "memory");
        }
        __syncthreads();

        const uint32_t st = sbase + s * STAGE_BYTES;
        const uint32_t sAh_ = st, sAl_ = st + 16384, sBh_ = st + 32768, sBl_ = st + 49152;

        #pragma unroll
        for (int ks = 0; ks < 4; ks++) {
            uint32_t bh[2][4], bl[2][4];
            #pragma unroll
            for (int ntp = 0; ntp < 2; ntp++) {
                const int rowB = b_row + ntp * 16;
                const uint32_t off = rowB * 128 + (((2 * ks + bg) ^ (rowB & 7)) << 4);
                ldsm4(bh[ntp], sBh_ + off);
                ldsm4(bl[ntp], sBl_ + off);
            }
            #pragma unroll
            for (int mt = 0; mt < 4; mt++) {
                const int rowA = a_row + mt * 16;
                const uint32_t off = rowA * 128 + (((2 * ks + ag) ^ (rowA & 7)) << 4);
                uint32_t ah[4], al[4];
                ldsm4(ah, sAh_ + off);
                ldsm4(al, sAl_ + off);
                #pragma unroll
                for (int nt = 0; nt < 4; nt++) {
                    uint32_t* fh = &bh[nt >> 1][(nt & 1) * 2];
                    uint32_t* fl = &bl[nt >> 1][(nt & 1) * 2];
                    mma16816(acc[mt][nt], ah, fh);
                    mma16816(acc[mt][nt], ah, fl);
                    mma16816(acc[mt][nt], al, fh);
                }
            }
        }
        __syncthreads();
    }
#undef LOAD_STAGE

    #pragma unroll
    for (int mt = 0; mt < 4; mt++) {
        #pragma unroll
        for (int nt = 0; nt < 4; nt++) {
            const int r = row0 + warp_m + mt * 16 + (lane >> 2);
            const int c = col0 + warp_n + nt * 8 + (lane & 3) * 2;
            const float b0 = bias ? bias[c] : 0.0f;
            const float b1 = bias ? bias[c + 1] : 0.0f;
            #pragma unroll
            for (int h = 0; h < 2; h++) {
                const long rr = r + h * 8;
                float v0 = acc[mt][nt][h * 2 + 0] + b0;
                float v1 = acc[mt][nt][h * 2 + 1] + b1;
                if (ACT) { v0 = gelu_exact(v0); v1 = gelu_exact(v1); }
                if (ACC) {
                    float2 old = *(const float2*)&C[rr * ldc + c];
                    v0 += old.x; v1 += old.y;
                    float2 nv = {v0, v1};
                    *(float2*)&C[rr * ldc + c] = nv;
                } else if (OSPLIT) {
                    __nv_bfloat16 h0, l0, h1, l1;
                    split2(v0, h0, l0);
                    split2(v1, h1, l1);
                    __nv_bfloat162 hv = {h0, h1}, lv = {l0, l1};
                    *(__nv_bfloat162*)&Oh[rr * ldc + c] = hv;
                    *(__nv_bfloat162*)&Ol[rr * ldc + c] = lv;
                } else {
                    float2 nv = {v0, v1};
                    *(float2*)&C[rr * ldc + c] = nv;
                }
            }
        }
    }
}

// ---------------- fp32 -> (hi, lo) bf16 split ----------------
__global__ void __launch_bounds__(256) split_k(
    const float* __restrict__ in, __nv_bfloat16* __restrict__ hi,
    __nv_bfloat16* __restrict__ lo, long n)
{
    for (long i = blockIdx.x * 256L + threadIdx.x; i < n; i += gridDim.x * 256L) {
        const float v = in[i];
        __nv_bfloat16 h, l;
        split2(v, h, l);
        hi[i] = h; lo[i] = l;
    }
}
__global__ void __launch_bounds__(256) split_x_k(
    const float* __restrict__ in, __nv_bfloat16* __restrict__ hi,
    __nv_bfloat16* __restrict__ lo)
{
    const long n = (long)M_SPAT * FEAT;
    for (long i = blockIdx.x * 256L + threadIdx.x; i < n; i += gridDim.x * 256L) {
        const long r = i >> 11, c = i & 2047;
        const float v = in[r * XROW + c];
        __nv_bfloat16 h, l;
        split2(v, h, l);
        hi[i] = h; lo[i] = l;
    }
}

// ---------------- LayerNorm -> hi/lo bf16 ----------------
__global__ void __launch_bounds__(256) ln_k(
    const float* __restrict__ X, const float* __restrict__ w,
    const float* __restrict__ b, __nv_bfloat16* __restrict__ Yh,
    __nv_bfloat16* __restrict__ Yl)
{
    const long t = blockIdx.x;
    const float* xr = X + t * EMBED;
    const int tid = threadIdx.x;

    float v0 = xr[tid], v1 = xr[tid + 256], v2 = xr[tid + 512];
    float s  = v0 + v1 + v2;
    float ss = v0 * v0 + v1 * v1 + v2 * v2;

    __shared__ float red[16];
    for (int o = 16; o; o >>= 1) {
        s  += __shfl_xor_sync(0xffffffffu, s,  o);
        ss += __shfl_xor_sync(0xffffffffu, ss, o);
    }
    const int warp = tid >> 5, lane = tid & 31;
    if (lane == 0) { red[warp] = s; red[warp + 8] = ss; }
    __syncthreads();
    __shared__ float smean, srstd;
    if (tid == 0) {
        float S = 0, SS = 0;
        #pragma unroll
        for (int i = 0; i < 8; i++) { S += red[i]; SS += red[i + 8]; }
        float m   = S * (1.0f / EMBED);
        float var = SS * (1.0f / EMBED) - m * m;
        smean = m;
        srstd = rsqrtf(var + 1e-6f);
    }
    __syncthreads();
    const float m = smean, r = srstd;
    __nv_bfloat16 h, l;
    float y;
    y = (v0 - m) * r * w[tid] + b[tid];
    split2(y, h, l); Yh[t * EMBED + tid] = h; Yl[t * EMBED + tid] = l;
    y = (v1 - m) * r * w[tid + 256] + b[tid + 256];
    split2(y, h, l); Yh[t * EMBED + tid + 256] = h; Yl[t * EMBED + tid + 256] = l;
    y = (v2 - m) * r * w[tid + 512] + b[tid + 512];
    split2(y, h, l); Yh[t * EMBED + tid + 512] = h; Yl[t * EMBED + tid + 512] = l;
}

// ---------------- attention -> hi/lo bf16 output ----------------
__global__ void __launch_bounds__(256) attn_k(
    const float* __restrict__ QKV, const float* __restrict__ MB,
    __nv_bfloat16* __restrict__ Oh, __nv_bfloat16* __restrict__ Ol)
{
    extern __shared__ float sm[];
    float* Qs = sm;
    float* Ks = sm + NTOK * HDIM;
    float* Vs = sm + 2 * NTOK * HDIM;
    __shared__ float probs[8][NTOK];
    __shared__ float mbs[NTOK];

    const int bh = blockIdx.x;
    const int b  = bh / HEADS, hh = bh % HEADS;
    const float* base = QKV + (long)b * NTOK * (3 * EMBED) + hh * HDIM;

    for (int idx = threadIdx.x; idx < NTOK * HDIM; idx += 256) {
        const int i = idx >> 6, c = idx & 63;
        const float* p = base + (long)i * (3 * EMBED) + c;
        Qs[idx] = p[0] * 0.125f;
        Ks[idx] = p[EMBED];
        Vs[idx] = p[2 * EMBED];
    }
    if (threadIdx.x < NTOK) mbs[threadIdx.x] = MB[b * NTOK + threadIdx.x];
    __syncthreads();

    const int warp = threadIdx.x >> 5, lane = threadIdx.x & 31;

    for (int i = warp; i < NTOK; i += 8) {
        int nk, fbase = 0;
        if (i == 0) nk = NTOK;
        else { const int f = (i - 1) / LTOK; fbase = 1 + f * LTOK; nk = LTOK + 1; }

        float sims[3];
        float mx = -1e30f;
        int s = 0;
        for (int t = lane; t < nk; t += 32, s++) {
            const int tok = (i == 0) ? t : (t == 0 ? 0 : fbase + t - 1);
            const float* kk = Ks + tok * HDIM;
            const float* qq = Qs + i * HDIM;
            float d = 0.0f;
            #pragma unroll
            for (int c = 0; c < HDIM; c++) d = fmaf(qq[c], kk[c], d);
            sims[s] = d + mbs[tok];
            mx = fmaxf(mx, sims[s]);
        }
        for (int o = 16; o; o >>= 1) mx = fmaxf(mx, __shfl_xor_sync(0xffffffffu, mx, o));
        float lsum = 0.0f;
        s = 0;
        for (int t = lane; t < nk; t += 32, s++) {
            const float p = expf(sims[s] - mx);
            probs[warp][t] = p;
            lsum += p;
        }
        for (int o = 16; o; o >>= 1) lsum += __shfl_xor_sync(0xffffffffu, lsum, o);
        const float inv = 1.0f / lsum;
        __syncwarp();

        float o0 = 0.0f, o1 = 0.0f;
        const int c0 = lane * 2;
        for (int t = 0; t < nk; t++) {
            const int tok = (i == 0) ? t : (t == 0 ? 0 : fbase + t - 1);
            const float p = probs[warp][t];
            o0 = fmaf(p, Vs[tok * HDIM + c0],     o0);
            o1 = fmaf(p, Vs[tok * HDIM + c0 + 1], o1);
        }
        const long oi = ((long)(b * NTOK + i)) * EMBED + hh * HDIM + c0;
        __nv_bfloat16 h, l;
        split2(o0 * inv, h, l); Oh[oi] = h;     Ol[oi] = l;
        split2(o1 * inv, h, l); Oh[oi + 1] = h; Ol[oi + 1] = l;
        __syncwarp();
    }
}

// ---------------- embed epilogue ----------------
__global__ void __launch_bounds__(256) embed_finish_k(
    const float* __restrict__ S, const float* __restrict__ x,
    const float* __restrict__ objb, const float* __restrict__ posb,
    const float* __restrict__ posW, const float* __restrict__ te,
    const int* __restrict__ xmask, float* __restrict__ X, float* __restrict__ MB)
{
    const int t = blockIdx.x;
    const int b = t / (FRAMES * LTOK);
    const int j = t % (FRAMES * LTOK);
    const int f = j / LTOK;

    __shared__ float xp[6];
    if (threadIdx.x < 6) xp[threadIdx.x] = x[(long)t * XROW + FEAT + threadIdx.x];
    __syncthreads();

    const long orow = ((long)b * NTOK + 1 + j) * EMBED;
    for (int e = threadIdx.x; e < EMBED; e += 256) {
        float v = S[(long)t * EMBED + e] + objb[e] + posb[e] + te[f * EMBED + e];
        #pragma unroll
        for (int k = 0; k < 6; k++) v = fmaf(xp[k], posW[e * 6 + k], v);
        X[orow + e] = v;
    }
    if (threadIdx.x == 0) MB[b * NTOK + 1 + j] = xmask[t] ? 0.0f : -100.0f;
}

__global__ void __launch_bounds__(256) cls_init_k(
    const float* __restrict__ cls_tok, const float* __restrict__ cls_pos,
    float* __restrict__ X, float* __restrict__ MB)
{
    const int b = blockIdx.x;
    for (int e = threadIdx.x; e < EMBED; e += 256)
        X[(long)b * NTOK * EMBED + e] = cls_tok[e] + cls_pos[e];
    if (threadIdx.x == 0) MB[b * NTOK] = 0.0f;
}

__global__ void __launch_bounds__(256) copy_mbias_k(
    const float* __restrict__ MB, float* __restrict__ out)
{
    const int i = blockIdx.x * 256 + threadIdx.x;
    if (i < M_ALL) out[i] = MB[i];
}

// ---------------- host orchestration ----------------
#define GEMM_SMEM (2 * STAGE_BYTES)   // 131072

extern "C" void kernel_launch(void* const* d_in, const int* in_sizes, int n_in,
                              void* d_out, int out_size)
{
    const float* x        = (const float*)d_in[0];
    const int*   x_mask   = (const int*)  d_in[1];
    const float* obj_W    = (const float*)d_in[2];
    const float* obj_b    = (const float*)d_in[3];
    const float* pos_W    = (const float*)d_in[4];
    const float* pos_b    = (const float*)d_in[5];
    const float* cls_tok  = (const float*)d_in[6];
    const float* cls_pos  = (const float*)d_in[7];
    const float* temporal = (const float*)d_in[8];
    const float* ln1_w    = (const float*)d_in[9];
    const float* ln1_b    = (const float*)d_in[10];
    const float* ln2_w    = (const float*)d_in[11];
    const float* ln2_b    = (const float*)d_in[12];
    const float* qkv_W    = (const float*)d_in[13];
    const float* qkv_b    = (const float*)d_in[14];
    const float* ap_W     = (const float*)d_in[15];
    const float* ap_b     = (const float*)d_in[16];
    const float* fc1_W    = (const float*)d_in[17];
    const float* fc1_b    = (const float*)d_in[18];
    const float* fc2_W    = (const float*)d_in[19];
    const float* fc2_b    = (const float*)d_in[20];
    const float* proj_W   = (const float*)d_in[21];

    float *gX, *gS, *gM;
    __nv_bfloat16 *gAh, *gAl, *gBh, *gBl, *gWh, *gWl;
    cudaGetSymbolAddress((void**)&gX, g_X);
    cudaGetSymbolAddress((void**)&gS, g_S);
    cudaGetSymbolAddress((void**)&gM, g_MB);
    cudaGetSymbolAddress((void**)&gAh, g_Ah);
    cudaGetSymbolAddress((void**)&gAl, g_Al);
    cudaGetSymbolAddress((void**)&gBh, g_Bh);
    cudaGetSymbolAddress((void**)&gBl, g_Bl);
    cudaGetSymbolAddress((void**)&gWh, g_Wh);
    cudaGetSymbolAddress((void**)&gWl, g_Wl);

    const int attn_smem = 3 * NTOK * HDIM * (int)sizeof(float);
    cudaFuncSetAttribute(attn_k, cudaFuncAttributeMaxDynamicSharedMemorySize, attn_smem);
    cudaFuncSetAttribute(gemm_mma<0,0,0>, cudaFuncAttributeMaxDynamicSharedMemorySize, GEMM_SMEM);
    cudaFuncSetAttribute(gemm_mma<0,1,0>, cudaFuncAttributeMaxDynamicSharedMemorySize, GEMM_SMEM);
    cudaFuncSetAttribute(gemm_mma<1,0,1>, cudaFuncAttributeMaxDynamicSharedMemorySize, GEMM_SMEM);

    // ---- weight conversion (once per call) ----
    split_k<<<2048, 256>>>(obj_W,  gWh + OFF_OBJ,  gWl + OFF_OBJ,  (long)EMBED * FEAT);
    split_k<<<2048, 256>>>(qkv_W,  gWh + OFF_QKV,  gWl + OFF_QKV,  (long)DEPTH * 3 * EMBED * EMBED);
    split_k<<<2048, 256>>>(ap_W,   gWh + OFF_AP,   gWl + OFF_AP,   (long)DEPTH * EMBED * EMBED);
    split_k<<<2048, 256>>>(fc1_W,  gWh + OFF_FC1,  gWl + OFF_FC1,  (long)DEPTH * 4 * EMBED * EMBED);
    split_k<<<2048, 256>>>(fc2_W,  gWh + OFF_FC2,  gWl + OFF_FC2,  (long)DEPTH * EMBED * 4 * EMBED);
    split_k<<<2048, 256>>>(proj_W, gWh + OFF_PROJ, gWl + OFF_PROJ, (long)OUTD * EMBED);

    // ---- embedding ----
    split_x_k<<<2048, 256>>>(x, gAh, gAl);
    gemm_mma<0,0,0><<<dim3(EMBED / 128, M_SPAT / 128), 256, GEMM_SMEM>>>(
        gAh, gAl, FEAT, gWh + OFF_OBJ, gWl + OFF_OBJ, FEAT,
        nullptr, gS, nullptr, nullptr, EMBED, FEAT);
    embed_finish_k<<<M_SPAT, 256>>>(gS, x, obj_b, pos_b, pos_W, temporal, x_mask, gX, gM);
    cls_init_k<<<BATCH, 256>>>(cls_tok, cls_pos, gX, gM);

    // ---- layers ----
    for (int l = 0; l < DEPTH; l++) {
        const __nv_bfloat16* qWh = gWh + OFF_QKV + (long)l * 3 * EMBED * EMBED;
        const __nv_bfloat16* qWl = gWl + OFF_QKV + (long)l * 3 * EMBED * EMBED;
        const __nv_bfloat16* aWh = gWh + OFF_AP  + (long)l * EMBED * EMBED;
        const __nv_bfloat16* aWl = gWl + OFF_AP  + (long)l * EMBED * EMBED;
        const __nv_bfloat16* f1h = gWh + OFF_FC1 + (long)l * 4 * EMBED * EMBED;
        const __nv_bfloat16* f1l = gWl + OFF_FC1 + (long)l * 4 * EMBED * EMBED;
        const __nv_bfloat16* f2h = gWh + OFF_FC2 + (long)l * EMBED * 4 * EMBED;
        const __nv_bfloat16* f2l = gWl + OFF_FC2 + (long)l * EMBED * 4 * EMBED;
        const float* qb  = qkv_b + (long)l * 3 * EMBED;
        const float* ab  = ap_b  + (long)l * EMBED;
        const float* f1b = fc1_b + (long)l * 4 * EMBED;
        const float* f2b = fc2_b + (long)l * EMBED;

        // ln1 -> (gBh, gBl)
        ln_k<<<M_ALL, 256>>>(gX, ln1_w + l * EMBED, ln1_b + l * EMBED, gBh, gBl);
        // qkv: S = B @ qW^T + qb (float)
        gemm_mma<0,0,0><<<dim3(3 * EMBED / 128, M_ALL / 128), 256, GEMM_SMEM>>>(
            gBh, gBl, EMBED, qWh, qWl, EMBED, qb, gS, nullptr, nullptr, 3 * EMBED, EMBED);
        // attention -> (gBh, gBl)
        attn_k<<<BATCH * HEADS, 256, attn_smem>>>(gS, gM, gBh, gBl);
        // X += B @ apW^T + ab
        gemm_mma<0,1,0><<<dim3(EMBED / 128, M_ALL / 128), 256, GEMM_SMEM>>>(
            gBh, gBl, EMBED, aWh, aWl, EMBED, ab, gX, nullptr, nullptr, EMBED, EMBED);
        // ln2 -> (gBh, gBl)
        ln_k<<<M_ALL, 256>>>(gX, ln2_w + l * EMBED, ln2_b + l * EMBED, gBh, gBl);
        // fc1: (gAh, gAl) <- gelu(B @ f1W^T + f1b) split   [distinct buffers: no aliasing]
        gemm_mma<1,0,1><<<dim3(4 * EMBED / 128, M_ALL / 128), 256, GEMM_SMEM>>>(
            gBh, gBl, EMBED, f1h, f1l, EMBED, f1b, nullptr, gAh, gAl, 4 * EMBED, EMBED);
        // X += H @ f2W^T + f2b
        gemm_mma<0,1,0><<<dim3(EMBED / 128, M_ALL / 128), 256, GEMM_SMEM>>>(
            gAh, gAl, 4 * EMBED, f2h, f2l, 4 * EMBED, f2b, gX, nullptr, nullptr, EMBED, 4 * EMBED);
    }

    // ---- head ----
    float* out = (float*)d_out;
    split_k<<<2048, 256>>>(gX, gBh, gBl, (long)M_ALL * EMBED);
    gemm_mma<0,0,0><<<dim3(OUTD / 128, M_ALL / 128), 256, GEMM_SMEM>>>(
        gBh, gBl, EMBED, gWh + OFF_PROJ, gWl + OFF_PROJ, EMBED,
        nullptr, out, nullptr, nullptr, OUTD, EMBED);

    if (out_size >= M_ALL * OUTD + M_ALL) {
        copy_mbias_k<<<(M_ALL + 255) / 256, 256>>>(gM, out + (long)M_ALL * OUTD);
    }
}

// round 5
// speedup vs baseline: 4.1650x; 1.0023x over previous
#include <cuda_runtime.h>
#include <cuda_bf16.h>
#include <math.h>
#include <stdint.h>

// ---------------- problem constants ----------------
#define BATCH   256
#define FRAMES  4
#define LTOK    20
#define NTOK    81
#define EMBED   768
#define HEADS   12
#define HDIM    64
#define DEPTH   12
#define FEAT    2048
#define XROW    2054
#define M_ALL   (BATCH * NTOK)          // 20736
#define M_SPAT  (BATCH * FRAMES * LTOK) // 20480
#define OUTD    256

// weight offsets (elements) in the packed bf16 weight buffers
#define OFF_OBJ  0L
#define OFF_QKV  1572864L
#define OFF_AP   22806528L
#define OFF_FC1  29884416L
#define OFF_FC2  58195968L
#define OFF_PROJ 86507520L
#define W_TOTAL  86704128L

// ---------------- scratch ----------------
__device__ float g_X[M_ALL * EMBED];
__device__ float g_S[M_ALL * 4 * EMBED];
__device__ float g_MB[M_ALL];
__device__ __nv_bfloat16 g_Ah[63700992];          // M_ALL*3072 (embed input / fc1 out)
__device__ __nv_bfloat16 g_Al[63700992];
__device__ __nv_bfloat16 g_Bh[M_ALL * EMBED];     // 768-wide activations
__device__ __nv_bfloat16 g_Bl[M_ALL * EMBED];
__device__ __nv_bfloat16 g_Wh[W_TOTAL];
__device__ __nv_bfloat16 g_Wl[W_TOTAL];

// ---------------- helpers ----------------
__device__ __forceinline__ uint32_t smem_u32(const void* p) {
    uint32_t a;
    asm("{ .reg .u64 t; cvta.to.shared.u64 t, %1; cvt.u32.u64 %0, t; }" : "=r"(a) : "l"(p));
    return a;
}
__device__ __forceinline__ void cpa16(uint32_t dst, const void* src) {
    asm volatile("cp.async.cg.shared.global [%0], [%1], 16;" :: "r"(dst), "l"(src));
}
__device__ __forceinline__ void ldsm4(uint32_t* r, uint32_t addr) {
    asm volatile("ldmatrix.sync.aligned.m8n8.x4.shared.b16 {%0,%1,%2,%3}, [%4];"
                 : "=r"(r[0]), "=r"(r[1]), "=r"(r[2]), "=r"(r[3]) : "r"(addr));
}
__device__ __forceinline__ void mma16816(float* c, const uint32_t* a, const uint32_t* b) {
    asm volatile(
        "mma.sync.aligned.m16n8k16.row.col.f32.bf16.bf16.f32 "
        "{%0,%1,%2,%3}, {%4,%5,%6,%7}, {%8,%9}, {%0,%1,%2,%3};"
        : "+f"(c[0]), "+f"(c[1]), "+f"(c[2]), "+f"(c[3])
        : "r"(a[0]), "r"(a[1]), "r"(a[2]), "r"(a[3]), "r"(b[0]), "r"(b[1]));
}
__device__ __forceinline__ float gelu_exact(float x) {
    return 0.5f * x * (1.0f + erff(x * 0.70710678118654752f));
}
__device__ __forceinline__ void split2(float v, __nv_bfloat16& h, __nv_bfloat16& l) {
    h = __float2bfloat16(v);
    l = __float2bfloat16(v - __bfloat162float(h));
}

// ---------------- bf16 hi/lo split GEMM on mma.sync, 3-stage pipeline ----------------
#define KC 64
#define STAGES 3
#define STAGE_BYTES 65536  // 4 buffers x 16KB (Ah Al Bh Bl), chunk 128x64 bf16 each

template<int ACT, int ACC, int OSPLIT>
__global__ void __launch_bounds__(256, 1) gemm_mma(
    const __nv_bfloat16* __restrict__ Ah, const __nv_bfloat16* __restrict__ Al, int lda,
    const __nv_bfloat16* __restrict__ Bh, const __nv_bfloat16* __restrict__ Bl, int ldw,
    const float* __restrict__ bias,
    float* __restrict__ C,
    __nv_bfloat16* __restrict__ Oh, __nv_bfloat16* __restrict__ Ol,
    int ldc, int K)
{
    extern __shared__ char smem[];
    const uint32_t sbase = smem_u32(smem);
    const int tid = threadIdx.x, wid = tid >> 5, lane = tid & 31;
    const int row0 = blockIdx.y * 128, col0 = blockIdx.x * 128;
    const int warp_m = (wid & 1) * 64, warp_n = (wid >> 1) * 32;

    const __nv_bfloat16* g0 = Ah + (long)row0 * lda;
    const __nv_bfloat16* g1 = Al + (long)row0 * lda;
    const __nv_bfloat16* g2 = Bh + (long)col0 * ldw;
    const __nv_bfloat16* g3 = Bl + (long)col0 * ldw;

    float acc[4][4][4];
    #pragma unroll
    for (int a = 0; a < 4; a++)
        #pragma unroll
        for (int b = 0; b < 4; b++)
            #pragma unroll
            for (int c = 0; c < 4; c++) acc[a][b][c] = 0.0f;

    const int id  = lane >> 3;
    const int rin = lane & 7;
    const int a_row = warp_m + ((id & 1) << 3) + rin;
    const int b_row = warp_n + ((id >> 1) << 3) + rin;
    const int ag = id >> 1;
    const int bg = id & 1;

    const int nk = K / KC;

#define LOAD_STAGE(stage, k0)                                                        \
    {                                                                                \
        const uint32_t st_ = sbase + (stage) * STAGE_BYTES;                          \
        _Pragma("unroll")                                                            \
        for (int i = 0; i < 4; i++) {                                                \
            const int c_ = tid + i * 256;                                            \
            const int row_ = c_ >> 3, gg_ = c_ & 7;                                  \
            const uint32_t ph_ = row_ * 128 + ((gg_ ^ (row_ & 7)) << 4);             \
            cpa16(st_ + ph_,          g0 + (long)row_ * lda + (k0) + gg_ * 8);       \
            cpa16(st_ + 16384 + ph_,  g1 + (long)row_ * lda + (k0) + gg_ * 8);       \
            cpa16(st_ + 32768 + ph_,  g2 + (long)row_ * ldw + (k0) + gg_ * 8);       \
            cpa16(st_ + 49152 + ph_,  g3 + (long)row_ * ldw + (k0) + gg_ * 8);       \
        }                                                                            \
        asm volatile("cp.async.commit_group;" ::: "memory");                         \
    }

    // prologue: fill 2 stages
    LOAD_STAGE(0, 0);
    if (nk > 1) LOAD_STAGE(1, KC);

    for (int ck = 0; ck < nk; ck++) {
        const int s = ck % STAGES;
        if (ck + 2 < nk) {
            LOAD_STAGE((ck + 2) % STAGES, (ck + 2) * KC);
            asm volatile("cp.async.wait_group 2;" ::: "memory");
        } else if (ck + 1 < nk) {
            asm volatile("cp.async.wait_group 1;" ::: "memory");
        } else {
            asm volatile("cp.async.wait_group 0;" ::: "memory");
        }
        __syncthreads();

        const uint32_t st = sbase + s * STAGE_BYTES;
        const uint32_t sAh_ = st, sAl_ = st + 16384, sBh_ = st + 32768, sBl_ = st + 49152;

        #pragma unroll
        for (int ks = 0; ks < 4; ks++) {
            uint32_t bh[2][4], bl[2][4];
            #pragma unroll
            for (int ntp = 0; ntp < 2; ntp++) {
                const int rowB = b_row + ntp * 16;
                const uint32_t off = rowB * 128 + (((2 * ks + bg) ^ (rowB & 7)) << 4);
                ldsm4(bh[ntp], sBh_ + off);
                ldsm4(bl[ntp], sBl_ + off);
            }
            #pragma unroll
            for (int mt = 0; mt < 4; mt++) {
                const int rowA = a_row + mt * 16;
                const uint32_t off = rowA * 128 + (((2 * ks + ag) ^ (rowA & 7)) << 4);
                uint32_t ah[4], al[4];
                ldsm4(ah, sAh_ + off);
                ldsm4(al, sAl_ + off);
                #pragma unroll
                for (int nt = 0; nt < 4; nt++) {
                    uint32_t* fh = &bh[nt >> 1][(nt & 1) * 2];
                    uint32_t* fl = &bl[nt >> 1][(nt & 1) * 2];
                    mma16816(acc[mt][nt], ah, fh);
                    mma16816(acc[mt][nt], ah, fl);
                    mma16816(acc[mt][nt], al, fh);
                }
            }
        }
        __syncthreads();
    }
#undef LOAD_STAGE

    #pragma unroll
    for (int mt = 0; mt < 4; mt++) {
        #pragma unroll
        for (int nt = 0; nt < 4; nt++) {
            const int r = row0 + warp_m + mt * 16 + (lane >> 2);
            const int c = col0 + warp_n + nt * 8 + (lane & 3) * 2;
            const float b0 = bias ? bias[c] : 0.0f;
            const float b1 = bias ? bias[c + 1] : 0.0f;
            #pragma unroll
            for (int h = 0; h < 2; h++) {
                const long rr = r + h * 8;
                float v0 = acc[mt][nt][h * 2 + 0] + b0;
                float v1 = acc[mt][nt][h * 2 + 1] + b1;
                if (ACT) { v0 = gelu_exact(v0); v1 = gelu_exact(v1); }
                if (ACC) {
                    float2 old = *(const float2*)&C[rr * ldc + c];
                    v0 += old.x; v1 += old.y;
                    float2 nv = {v0, v1};
                    *(float2*)&C[rr * ldc + c] = nv;
                } else if (OSPLIT) {
                    __nv_bfloat16 h0, l0, h1, l1;
                    split2(v0, h0, l0);
                    split2(v1, h1, l1);
                    __nv_bfloat162 hv = {h0, h1}, lv = {l0, l1};
                    *(__nv_bfloat162*)&Oh[rr * ldc + c] = hv;
                    *(__nv_bfloat162*)&Ol[rr * ldc + c] = lv;
                } else {
                    float2 nv = {v0, v1};
                    *(float2*)&C[rr * ldc + c] = nv;
                }
            }
        }
    }
}

// ---------------- fp32 -> (hi, lo) bf16 split ----------------
__global__ void __launch_bounds__(256) split_k(
    const float* __restrict__ in, __nv_bfloat16* __restrict__ hi,
    __nv_bfloat16* __restrict__ lo, long n)
{
    for (long i = blockIdx.x * 256L + threadIdx.x; i < n; i += gridDim.x * 256L) {
        const float v = in[i];
        __nv_bfloat16 h, l;
        split2(v, h, l);
        hi[i] = h; lo[i] = l;
    }
}
__global__ void __launch_bounds__(256) split_x_k(
    const float* __restrict__ in, __nv_bfloat16* __restrict__ hi,
    __nv_bfloat16* __restrict__ lo)
{
    const long n = (long)M_SPAT * FEAT;
    for (long i = blockIdx.x * 256L + threadIdx.x; i < n; i += gridDim.x * 256L) {
        const long r = i >> 11, c = i & 2047;
        const float v = in[r * XROW + c];
        __nv_bfloat16 h, l;
        split2(v, h, l);
        hi[i] = h; lo[i] = l;
    }
}

// ---------------- LayerNorm -> hi/lo bf16 ----------------
__global__ void __launch_bounds__(256) ln_k(
    const float* __restrict__ X, const float* __restrict__ w,
    const float* __restrict__ b, __nv_bfloat16* __restrict__ Yh,
    __nv_bfloat16* __restrict__ Yl)
{
    const long t = blockIdx.x;
    const float* xr = X + t * EMBED;
    const int tid = threadIdx.x;

    float v0 = xr[tid], v1 = xr[tid + 256], v2 = xr[tid + 512];
    float s  = v0 + v1 + v2;
    float ss = v0 * v0 + v1 * v1 + v2 * v2;

    __shared__ float red[16];
    for (int o = 16; o; o >>= 1) {
        s  += __shfl_xor_sync(0xffffffffu, s,  o);
        ss += __shfl_xor_sync(0xffffffffu, ss, o);
    }
    const int warp = tid >> 5, lane = tid & 31;
    if (lane == 0) { red[warp] = s; red[warp + 8] = ss; }
    __syncthreads();
    __shared__ float smean, srstd;
    if (tid == 0) {
        float S = 0, SS = 0;
        #pragma unroll
        for (int i = 0; i < 8; i++) { S += red[i]; SS += red[i + 8]; }
        float m   = S * (1.0f / EMBED);
        float var = SS * (1.0f / EMBED) - m * m;
        smean = m;
        srstd = rsqrtf(var + 1e-6f);
    }
    __syncthreads();
    const float m = smean, r = srstd;
    __nv_bfloat16 h, l;
    float y;
    y = (v0 - m) * r * w[tid] + b[tid];
    split2(y, h, l); Yh[t * EMBED + tid] = h; Yl[t * EMBED + tid] = l;
    y = (v1 - m) * r * w[tid + 256] + b[tid + 256];
    split2(y, h, l); Yh[t * EMBED + tid + 256] = h; Yl[t * EMBED + tid + 256] = l;
    y = (v2 - m) * r * w[tid + 512] + b[tid + 512];
    split2(y, h, l); Yh[t * EMBED + tid + 512] = h; Yl[t * EMBED + tid + 512] = l;
}

// ---------------- attention -> hi/lo bf16 output ----------------
__global__ void __launch_bounds__(256) attn_k(
    const float* __restrict__ QKV, const float* __restrict__ MB,
    __nv_bfloat16* __restrict__ Oh, __nv_bfloat16* __restrict__ Ol)
{
    extern __shared__ float sm[];
    float* Qs = sm;
    float* Ks = sm + NTOK * HDIM;
    float* Vs = sm + 2 * NTOK * HDIM;
    __shared__ float probs[8][NTOK];
    __shared__ float mbs[NTOK];

    const int bh = blockIdx.x;
    const int b  = bh / HEADS, hh = bh % HEADS;
    const float* base = QKV + (long)b * NTOK * (3 * EMBED) + hh * HDIM;

    for (int idx = threadIdx.x; idx < NTOK * HDIM; idx += 256) {
        const int i = idx >> 6, c = idx & 63;
        const float* p = base + (long)i * (3 * EMBED) + c;
        Qs[idx] = p[0] * 0.125f;
        Ks[idx] = p[EMBED];
        Vs[idx] = p[2 * EMBED];
    }
    if (threadIdx.x < NTOK) mbs[threadIdx.x] = MB[b * NTOK + threadIdx.x];
    __syncthreads();

    const int warp = threadIdx.x >> 5, lane = threadIdx.x & 31;

    for (int i = warp; i < NTOK; i += 8) {
        int nk, fbase = 0;
        if (i == 0) nk = NTOK;
        else { const int f = (i - 1) / LTOK; fbase = 1 + f * LTOK; nk = LTOK + 1; }

        float sims[3];
        float mx = -1e30f;
        int s = 0;
        for (int t = lane; t < nk; t += 32, s++) {
            const int tok = (i == 0) ? t : (t == 0 ? 0 : fbase + t - 1);
            const float* kk = Ks + tok * HDIM;
            const float* qq = Qs + i * HDIM;
            float d = 0.0f;
            #pragma unroll
            for (int c = 0; c < HDIM; c++) d = fmaf(qq[c], kk[c], d);
            sims[s] = d + mbs[tok];
            mx = fmaxf(mx, sims[s]);
        }
        for (int o = 16; o; o >>= 1) mx = fmaxf(mx, __shfl_xor_sync(0xffffffffu, mx, o));
        float lsum = 0.0f;
        s = 0;
        for (int t = lane; t < nk; t += 32, s++) {
            const float p = expf(sims[s] - mx);
            probs[warp][t] = p;
            lsum += p;
        }
        for (int o = 16; o; o >>= 1) lsum += __shfl_xor_sync(0xffffffffu, lsum, o);
        const float inv = 1.0f / lsum;
        __syncwarp();

        float o0 = 0.0f, o1 = 0.0f;
        const int c0 = lane * 2;
        for (int t = 0; t < nk; t++) {
            const int tok = (i == 0) ? t : (t == 0 ? 0 : fbase + t - 1);
            const float p = probs[warp][t];
            o0 = fmaf(p, Vs[tok * HDIM + c0],     o0);
            o1 = fmaf(p, Vs[tok * HDIM + c0 + 1], o1);
        }
        const long oi = ((long)(b * NTOK + i)) * EMBED + hh * HDIM + c0;
        __nv_bfloat16 h, l;
        split2(o0 * inv, h, l); Oh[oi] = h;     Ol[oi] = l;
        split2(o1 * inv, h, l); Oh[oi + 1] = h; Ol[oi + 1] = l;
        __syncwarp();
    }
}

// ---------------- embed epilogue ----------------
__global__ void __launch_bounds__(256) embed_finish_k(
    const float* __restrict__ S, const float* __restrict__ x,
    const float* __restrict__ objb, const float* __restrict__ posb,
    const float* __restrict__ posW, const float* __restrict__ te,
    const int* __restrict__ xmask, float* __restrict__ X, float* __restrict__ MB)
{
    const int t = blockIdx.x;
    const int b = t / (FRAMES * LTOK);
    const int j = t % (FRAMES * LTOK);
    const int f = j / LTOK;

    __shared__ float xp[6];
    if (threadIdx.x < 6) xp[threadIdx.x] = x[(long)t * XROW + FEAT + threadIdx.x];
    __syncthreads();

    const long orow = ((long)b * NTOK + 1 + j) * EMBED;
    for (int e = threadIdx.x; e < EMBED; e += 256) {
        float v = S[(long)t * EMBED + e] + objb[e] + posb[e] + te[f * EMBED + e];
        #pragma unroll
        for (int k = 0; k < 6; k++) v = fmaf(xp[k], posW[e * 6 + k], v);
        X[orow + e] = v;
    }
    if (threadIdx.x == 0) MB[b * NTOK + 1 + j] = xmask[t] ? 0.0f : -100.0f;
}

__global__ void __launch_bounds__(256) cls_init_k(
    const float* __restrict__ cls_tok, const float* __restrict__ cls_pos,
    float* __restrict__ X, float* __restrict__ MB)
{
    const int b = blockIdx.x;
    for (int e = threadIdx.x; e < EMBED; e += 256)
        X[(long)b * NTOK * EMBED + e] = cls_tok[e] + cls_pos[e];
    if (threadIdx.x == 0) MB[b * NTOK] = 0.0f;
}

__global__ void __launch_bounds__(256) copy_mbias_k(
    const float* __restrict__ MB, float* __restrict__ out)
{
    const int i = blockIdx.x * 256 + threadIdx.x;
    if (i < M_ALL) out[i] = MB[i];
}

// ---------------- host orchestration ----------------
#define GEMM_SMEM (STAGES * STAGE_BYTES)   // 196608

extern "C" void kernel_launch(void* const* d_in, const int* in_sizes, int n_in,
                              void* d_out, int out_size)
{
    const float* x        = (const float*)d_in[0];
    const int*   x_mask   = (const int*)  d_in[1];
    const float* obj_W    = (const float*)d_in[2];
    const float* obj_b    = (const float*)d_in[3];
    const float* pos_W    = (const float*)d_in[4];
    const float* pos_b    = (const float*)d_in[5];
    const float* cls_tok  = (const float*)d_in[6];
    const float* cls_pos  = (const float*)d_in[7];
    const float* temporal = (const float*)d_in[8];
    const float* ln1_w    = (const float*)d_in[9];
    const float* ln1_b    = (const float*)d_in[10];
    const float* ln2_w    = (const float*)d_in[11];
    const float* ln2_b    = (const float*)d_in[12];
    const float* qkv_W    = (const float*)d_in[13];
    const float* qkv_b    = (const float*)d_in[14];
    const float* ap_W     = (const float*)d_in[15];
    const float* ap_b     = (const float*)d_in[16];
    const float* fc1_W    = (const float*)d_in[17];
    const float* fc1_b    = (const float*)d_in[18];
    const float* fc2_W    = (const float*)d_in[19];
    const float* fc2_b    = (const float*)d_in[20];
    const float* proj_W   = (const float*)d_in[21];

    float *gX, *gS, *gM;
    __nv_bfloat16 *gAh, *gAl, *gBh, *gBl, *gWh, *gWl;
    cudaGetSymbolAddress((void**)&gX, g_X);
    cudaGetSymbolAddress((void**)&gS, g_S);
    cudaGetSymbolAddress((void**)&gM, g_MB);
    cudaGetSymbolAddress((void**)&gAh, g_Ah);
    cudaGetSymbolAddress((void**)&gAl, g_Al);
    cudaGetSymbolAddress((void**)&gBh, g_Bh);
    cudaGetSymbolAddress((void**)&gBl, g_Bl);
    cudaGetSymbolAddress((void**)&gWh, g_Wh);
    cudaGetSymbolAddress((void**)&gWl, g_Wl);

    const int attn_smem = 3 * NTOK * HDIM * (int)sizeof(float);
    cudaFuncSetAttribute(attn_k, cudaFuncAttributeMaxDynamicSharedMemorySize, attn_smem);
    cudaFuncSetAttribute(gemm_mma<0,0,0>, cudaFuncAttributeMaxDynamicSharedMemorySize, GEMM_SMEM);
    cudaFuncSetAttribute(gemm_mma<0,1,0>, cudaFuncAttributeMaxDynamicSharedMemorySize, GEMM_SMEM);
    cudaFuncSetAttribute(gemm_mma<1,0,1>, cudaFuncAttributeMaxDynamicSharedMemorySize, GEMM_SMEM);

    // ---- weight conversion (once per call) ----
    split_k<<<2048, 256>>>(obj_W,  gWh + OFF_OBJ,  gWl + OFF_OBJ,  (long)EMBED * FEAT);
    split_k<<<2048, 256>>>(qkv_W,  gWh + OFF_QKV,  gWl + OFF_QKV,  (long)DEPTH * 3 * EMBED * EMBED);
    split_k<<<2048, 256>>>(ap_W,   gWh + OFF_AP,   gWl + OFF_AP,   (long)DEPTH * EMBED * EMBED);
    split_k<<<2048, 256>>>(fc1_W,  gWh + OFF_FC1,  gWl + OFF_FC1,  (long)DEPTH * 4 * EMBED * EMBED);
    split_k<<<2048, 256>>>(fc2_W,  gWh + OFF_FC2,  gWl + OFF_FC2,  (long)DEPTH * EMBED * 4 * EMBED);
    split_k<<<2048, 256>>>(proj_W, gWh + OFF_PROJ, gWl + OFF_PROJ, (long)OUTD * EMBED);

    // ---- embedding ----
    split_x_k<<<2048, 256>>>(x, gAh, gAl);
    gemm_mma<0,0,0><<<dim3(EMBED / 128, M_SPAT / 128), 256, GEMM_SMEM>>>(
        gAh, gAl, FEAT, gWh + OFF_OBJ, gWl + OFF_OBJ, FEAT,
        nullptr, gS, nullptr, nullptr, EMBED, FEAT);
    embed_finish_k<<<M_SPAT, 256>>>(gS, x, obj_b, pos_b, pos_W, temporal, x_mask, gX, gM);
    cls_init_k<<<BATCH, 256>>>(cls_tok, cls_pos, gX, gM);

    // ---- layers ----
    for (int l = 0; l < DEPTH; l++) {
        const __nv_bfloat16* qWh = gWh + OFF_QKV + (long)l * 3 * EMBED * EMBED;
        const __nv_bfloat16* qWl = gWl + OFF_QKV + (long)l * 3 * EMBED * EMBED;
        const __nv_bfloat16* aWh = gWh + OFF_AP  + (long)l * EMBED * EMBED;
        const __nv_bfloat16* aWl = gWl + OFF_AP  + (long)l * EMBED * EMBED;
        const __nv_bfloat16* f1h = gWh + OFF_FC1 + (long)l * 4 * EMBED * EMBED;
        const __nv_bfloat16* f1l = gWl + OFF_FC1 + (long)l * 4 * EMBED * EMBED;
        const __nv_bfloat16* f2h = gWh + OFF_FC2 + (long)l * EMBED * 4 * EMBED;
        const __nv_bfloat16* f2l = gWl + OFF_FC2 + (long)l * EMBED * 4 * EMBED;
        const float* qb  = qkv_b + (long)l * 3 * EMBED;
        const float* ab  = ap_b  + (long)l * EMBED;
        const float* f1b = fc1_b + (long)l * 4 * EMBED;
        const float* f2b = fc2_b + (long)l * EMBED;

        // ln1 -> (gBh, gBl)
        ln_k<<<M_ALL, 256>>>(gX, ln1_w + l * EMBED, ln1_b + l * EMBED, gBh, gBl);
        // qkv: S = B @ qW^T + qb (float)
        gemm_mma<0,0,0><<<dim3(3 * EMBED / 128, M_ALL / 128), 256, GEMM_SMEM>>>(
            gBh, gBl, EMBED, qWh, qWl, EMBED, qb, gS, nullptr, nullptr, 3 * EMBED, EMBED);
        // attention -> (gBh, gBl)
        attn_k<<<BATCH * HEADS, 256, attn_smem>>>(gS, gM, gBh, gBl);
        // X += B @ apW^T + ab
        gemm_mma<0,1,0><<<dim3(EMBED / 128, M_ALL / 128), 256, GEMM_SMEM>>>(
            gBh, gBl, EMBED, aWh, aWl, EMBED, ab, gX, nullptr, nullptr, EMBED, EMBED);
        // ln2 -> (gBh, gBl)
        ln_k<<<M_ALL, 256>>>(gX, ln2_w + l * EMBED, ln2_b + l * EMBED, gBh, gBl);
        // fc1: (gAh, gAl) <- gelu(B @ f1W^T + f1b) split
        gemm_mma<1,0,1><<<dim3(4 * EMBED / 128, M_ALL / 128), 256, GEMM_SMEM>>>(
            gBh, gBl, EMBED, f1h, f1l, EMBED, f1b, nullptr, gAh, gAl, 4 * EMBED, EMBED);
        // X += H @ f2W^T + f2b
        gemm_mma<0,1,0><<<dim3(EMBED / 128, M_ALL / 128), 256, GEMM_SMEM>>>(
            gAh, gAl, 4 * EMBED, f2h, f2l, 4 * EMBED, f2b, gX, nullptr, nullptr, EMBED, 4 * EMBED);
    }

    // ---- head ----
    float* out = (float*)d_out;
    split_k<<<2048, 256>>>(gX, gBh, gBl, (long)M_ALL * EMBED);
    gemm_mma<0,0,0><<<dim3(OUTD / 128, M_ALL / 128), 256, GEMM_SMEM>>>(
        gBh, gBl, EMBED, gWh + OFF_PROJ, gWl + OFF_PROJ, EMBED,
        nullptr, out, nullptr, nullptr, OUTD, EMBED);

    if (out_size >= M_ALL * OUTD + M_ALL) {
        copy_mbias_k<<<(M_ALL + 255) / 256, 256>>>(gM, out + (long)M_ALL * OUTD);
    }
}

// round 6
// speedup vs baseline: 4.3334x; 1.0404x over previous
#include <cuda_runtime.h>
#include <cuda_bf16.h>
#include <math.h>
#include <stdint.h>

// ---------------- problem constants ----------------
#define BATCH   256
#define FRAMES  4
#define LTOK    20
#define NTOK    81
#define EMBED   768
#define HEADS   12
#define HDIM    64
#define DEPTH   12
#define FEAT    2048
#define XROW    2054
#define M_ALL   (BATCH * NTOK)          // 20736
#define M_SPAT  (BATCH * FRAMES * LTOK) // 20480
#define OUTD    256

// weight offsets (elements) in the packed bf16 weight buffers
#define OFF_OBJ  0L
#define OFF_QKV  1572864L
#define OFF_AP   22806528L
#define OFF_FC1  29884416L
#define OFF_FC2  58195968L
#define OFF_PROJ 86507520L
#define W_TOTAL  86704128L

// ---------------- scratch ----------------
__device__ float g_X[M_ALL * EMBED];
__device__ float g_S[M_ALL * 4 * EMBED];
__device__ float g_MB[M_ALL];
__device__ __nv_bfloat16 g_Ah[63700992];          // M_ALL*3072 (embed input / fc1 out)
__device__ __nv_bfloat16 g_Al[63700992];
__device__ __nv_bfloat16 g_Bh[M_ALL * EMBED];     // 768-wide activations
__device__ __nv_bfloat16 g_Bl[M_ALL * EMBED];
__device__ __nv_bfloat16 g_Wh[W_TOTAL];
__device__ __nv_bfloat16 g_Wl[W_TOTAL];

// ---------------- helpers ----------------
__device__ __forceinline__ uint32_t smem_u32(const void* p) {
    uint32_t a;
    asm("{ .reg .u64 t; cvta.to.shared.u64 t, %1; cvt.u32.u64 %0, t; }" : "=r"(a) : "l"(p));
    return a;
}
__device__ __forceinline__ void cpa16(uint32_t dst, const void* src) {
    asm volatile("cp.async.cg.shared.global [%0], [%1], 16;" :: "r"(dst), "l"(src));
}
__device__ __forceinline__ void ldsm4(uint32_t* r, uint32_t addr) {
    asm volatile("ldmatrix.sync.aligned.m8n8.x4.shared.b16 {%0,%1,%2,%3}, [%4];"
                 : "=r"(r[0]), "=r"(r[1]), "=r"(r[2]), "=r"(r[3]) : "r"(addr));
}
__device__ __forceinline__ void mma16816(float* c, const uint32_t* a, const uint32_t* b) {
    asm volatile(
        "mma.sync.aligned.m16n8k16.row.col.f32.bf16.bf16.f32 "
        "{%0,%1,%2,%3}, {%4,%5,%6,%7}, {%8,%9}, {%0,%1,%2,%3};"
        : "+f"(c[0]), "+f"(c[1]), "+f"(c[2]), "+f"(c[3])
        : "r"(a[0]), "r"(a[1]), "r"(a[2]), "r"(a[3]), "r"(b[0]), "r"(b[1]));
}
__device__ __forceinline__ float gelu_exact(float x) {
    return 0.5f * x * (1.0f + erff(x * 0.70710678118654752f));
}
__device__ __forceinline__ void split2(float v, __nv_bfloat16& h, __nv_bfloat16& l) {
    h = __float2bfloat16(v);
    l = __float2bfloat16(v - __bfloat162float(h));
}

// KC=32 tile layout: logical 128 rows x 32 cols bf16 (64B/row) packed as
// 64 physical rows x 128B.  addr(r, g) = (r>>1)*128 + ((( ((r&1)<<2) | g ) ^ ((r>>1)&7)) << 4)
// Verified conflict-free for ldmatrix octets (distinct 16B slots for all 8 lanes).
__device__ __forceinline__ uint32_t tile_off(int r, int g) {
    const int p = r >> 1;
    const int x = ((((r & 1) << 2) | g) ^ (p & 7));
    return (uint32_t)((p << 7) + (x << 4));
}

// ---------------- bf16 hi/lo split GEMM on mma.sync, KC=32, 3 stages, 2 CTA/SM ----
#define KC 32
#define STAGES 3
#define STAGE_BYTES 32768  // 4 buffers x 8KB

template<int ACT, int ACC, int OSPLIT>
__global__ void __launch_bounds__(256, 2) gemm_mma(
    const __nv_bfloat16* __restrict__ Ah, const __nv_bfloat16* __restrict__ Al, int lda,
    const __nv_bfloat16* __restrict__ Bh, const __nv_bfloat16* __restrict__ Bl, int ldw,
    const float* __restrict__ bias,
    float* __restrict__ C,
    __nv_bfloat16* __restrict__ Oh, __nv_bfloat16* __restrict__ Ol,
    int ldc, int K)
{
    extern __shared__ char smem[];
    const uint32_t sbase = smem_u32(smem);
    const int tid = threadIdx.x, wid = tid >> 5, lane = tid & 31;
    const int row0 = blockIdx.y * 128, col0 = blockIdx.x * 128;
    const int warp_m = (wid & 1) * 64, warp_n = (wid >> 1) * 32;

    const __nv_bfloat16* g0 = Ah + (long)row0 * lda;
    const __nv_bfloat16* g1 = Al + (long)row0 * lda;
    const __nv_bfloat16* g2 = Bh + (long)col0 * ldw;
    const __nv_bfloat16* g3 = Bl + (long)col0 * ldw;

    float acc[4][4][4];
    #pragma unroll
    for (int a = 0; a < 4; a++)
        #pragma unroll
        for (int b = 0; b < 4; b++)
            #pragma unroll
            for (int c = 0; c < 4; c++) acc[a][b][c] = 0.0f;

    const int id  = lane >> 3;
    const int rin = lane & 7;
    const int a_row = warp_m + ((id & 1) << 3) + rin;
    const int b_row = warp_n + ((id >> 1) << 3) + rin;
    const int ag = id >> 1;   // 0/1 -> k subgroup within 32 (g = 2*ks + ag)
    const int bg = id & 1;

    // cp.async indices: chunk c = tid + i*256, row = c>>2, g = c&3 (512 chunks/matrix)
    const int l_row0 = tid >> 2,          l_g0 = tid & 3;
    const int l_row1 = (tid + 256) >> 2,  l_g1 = tid & 3;
    const uint32_t l_off0 = tile_off(l_row0, l_g0);
    const uint32_t l_off1 = tile_off(l_row1, l_g1);

    const int nk = K / KC;

#define LOAD_STAGE(stage, k0)                                                        \
    {                                                                                \
        const uint32_t st_ = sbase + (stage) * STAGE_BYTES;                          \
        cpa16(st_ + l_off0,          g0 + (long)l_row0 * lda + (k0) + l_g0 * 8);     \
        cpa16(st_ + l_off1,          g0 + (long)l_row1 * lda + (k0) + l_g1 * 8);     \
        cpa16(st_ + 8192  + l_off0,  g1 + (long)l_row0 * lda + (k0) + l_g0 * 8);     \
        cpa16(st_ + 8192  + l_off1,  g1 + (long)l_row1 * lda + (k0) + l_g1 * 8);     \
        cpa16(st_ + 16384 + l_off0,  g2 + (long)l_row0 * ldw + (k0) + l_g0 * 8);     \
        cpa16(st_ + 16384 + l_off1,  g2 + (long)l_row1 * ldw + (k0) + l_g1 * 8);     \
        cpa16(st_ + 24576 + l_off0,  g3 + (long)l_row0 * ldw + (k0) + l_g0 * 8);     \
        cpa16(st_ + 24576 + l_off1,  g3 + (long)l_row1 * ldw + (k0) + l_g1 * 8);     \
        asm volatile("cp.async.commit_group;" ::: "memory");                         \
    }

    LOAD_STAGE(0, 0);
    if (nk > 1) LOAD_STAGE(1, KC);

    for (int ck = 0; ck < nk; ck++) {
        const int s = ck % STAGES;
        if (ck + 2 < nk) {
            LOAD_STAGE((ck + 2) % STAGES, (ck + 2) * KC);
            asm volatile("cp.async.wait_group 2;" ::: "memory");
        } else if (ck + 1 < nk) {
            asm volatile("cp.async.wait_group 1;" ::: "memory");
        } else {
            asm volatile("cp.async.wait_group 0;" ::: "memory");
        }
        __syncthreads();

        const uint32_t st = sbase + s * STAGE_BYTES;
        const uint32_t sAh_ = st, sAl_ = st + 8192, sBh_ = st + 16384, sBl_ = st + 24576;

        #pragma unroll
        for (int ks = 0; ks < 2; ks++) {
            uint32_t bh[2][4], bl[2][4];
            #pragma unroll
            for (int ntp = 0; ntp < 2; ntp++) {
                const uint32_t off = tile_off(b_row + ntp * 16, 2 * ks + bg);
                ldsm4(bh[ntp], sBh_ + off);
                ldsm4(bl[ntp], sBl_ + off);
            }
            #pragma unroll
            for (int mt = 0; mt < 4; mt++) {
                const uint32_t off = tile_off(a_row + mt * 16, 2 * ks + ag);
                uint32_t ah[4], al[4];
                ldsm4(ah, sAh_ + off);
                ldsm4(al, sAl_ + off);
                #pragma unroll
                for (int nt = 0; nt < 4; nt++) {
                    uint32_t* fh = &bh[nt >> 1][(nt & 1) * 2];
                    uint32_t* fl = &bl[nt >> 1][(nt & 1) * 2];
                    mma16816(acc[mt][nt], ah, fh);
                    mma16816(acc[mt][nt], ah, fl);
                    mma16816(acc[mt][nt], al, fh);
                }
            }
        }
        __syncthreads();
    }
#undef LOAD_STAGE

    #pragma unroll
    for (int mt = 0; mt < 4; mt++) {
        #pragma unroll
        for (int nt = 0; nt < 4; nt++) {
            const int r = row0 + warp_m + mt * 16 + (lane >> 2);
            const int c = col0 + warp_n + nt * 8 + (lane & 3) * 2;
            const float b0 = bias ? bias[c] : 0.0f;
            const float b1 = bias ? bias[c + 1] : 0.0f;
            #pragma unroll
            for (int h = 0; h < 2; h++) {
                const long rr = r + h * 8;
                float v0 = acc[mt][nt][h * 2 + 0] + b0;
                float v1 = acc[mt][nt][h * 2 + 1] + b1;
                if (ACT) { v0 = gelu_exact(v0); v1 = gelu_exact(v1); }
                if (ACC) {
                    float2 old = *(const float2*)&C[rr * ldc + c];
                    v0 += old.x; v1 += old.y;
                    float2 nv = {v0, v1};
                    *(float2*)&C[rr * ldc + c] = nv;
                } else if (OSPLIT) {
                    __nv_bfloat16 h0, l0, h1, l1;
                    split2(v0, h0, l0);
                    split2(v1, h1, l1);
                    __nv_bfloat162 hv = {h0, h1}, lv = {l0, l1};
                    *(__nv_bfloat162*)&Oh[rr * ldc + c] = hv;
                    *(__nv_bfloat162*)&Ol[rr * ldc + c] = lv;
                } else {
                    float2 nv = {v0, v1};
                    *(float2*)&C[rr * ldc + c] = nv;
                }
            }
        }
    }
}

// ---------------- fp32 -> (hi, lo) bf16 split ----------------
__global__ void __launch_bounds__(256) split_k(
    const float* __restrict__ in, __nv_bfloat16* __restrict__ hi,
    __nv_bfloat16* __restrict__ lo, long n)
{
    for (long i = blockIdx.x * 256L + threadIdx.x; i < n; i += gridDim.x * 256L) {
        const float v = in[i];
        __nv_bfloat16 h, l;
        split2(v, h, l);
        hi[i] = h; lo[i] = l;
    }
}
__global__ void __launch_bounds__(256) split_x_k(
    const float* __restrict__ in, __nv_bfloat16* __restrict__ hi,
    __nv_bfloat16* __restrict__ lo)
{
    const long n = (long)M_SPAT * FEAT;
    for (long i = blockIdx.x * 256L + threadIdx.x; i < n; i += gridDim.x * 256L) {
        const long r = i >> 11, c = i & 2047;
        const float v = in[r * XROW + c];
        __nv_bfloat16 h, l;
        split2(v, h, l);
        hi[i] = h; lo[i] = l;
    }
}

// ---------------- LayerNorm -> hi/lo bf16 ----------------
__global__ void __launch_bounds__(256) ln_k(
    const float* __restrict__ X, const float* __restrict__ w,
    const float* __restrict__ b, __nv_bfloat16* __restrict__ Yh,
    __nv_bfloat16* __restrict__ Yl)
{
    const long t = blockIdx.x;
    const float* xr = X + t * EMBED;
    const int tid = threadIdx.x;

    float v0 = xr[tid], v1 = xr[tid + 256], v2 = xr[tid + 512];
    float s  = v0 + v1 + v2;
    float ss = v0 * v0 + v1 * v1 + v2 * v2;

    __shared__ float red[16];
    for (int o = 16; o; o >>= 1) {
        s  += __shfl_xor_sync(0xffffffffu, s,  o);
        ss += __shfl_xor_sync(0xffffffffu, ss, o);
    }
    const int warp = tid >> 5, lane = tid & 31;
    if (lane == 0) { red[warp] = s; red[warp + 8] = ss; }
    __syncthreads();
    __shared__ float smean, srstd;
    if (tid == 0) {
        float S = 0, SS = 0;
        #pragma unroll
        for (int i = 0; i < 8; i++) { S += red[i]; SS += red[i + 8]; }
        float m   = S * (1.0f / EMBED);
        float var = SS * (1.0f / EMBED) - m * m;
        smean = m;
        srstd = rsqrtf(var + 1e-6f);
    }
    __syncthreads();
    const float m = smean, r = srstd;
    __nv_bfloat16 h, l;
    float y;
    y = (v0 - m) * r * w[tid] + b[tid];
    split2(y, h, l); Yh[t * EMBED + tid] = h; Yl[t * EMBED + tid] = l;
    y = (v1 - m) * r * w[tid + 256] + b[tid + 256];
    split2(y, h, l); Yh[t * EMBED + tid + 256] = h; Yl[t * EMBED + tid + 256] = l;
    y = (v2 - m) * r * w[tid + 512] + b[tid + 512];
    split2(y, h, l); Yh[t * EMBED + tid + 512] = h; Yl[t * EMBED + tid + 512] = l;
}

// ---------------- attention -> hi/lo bf16 output ----------------
__global__ void __launch_bounds__(256) attn_k(
    const float* __restrict__ QKV, const float* __restrict__ MB,
    __nv_bfloat16* __restrict__ Oh, __nv_bfloat16* __restrict__ Ol)
{
    extern __shared__ float sm[];
    float* Qs = sm;
    float* Ks = sm + NTOK * HDIM;
    float* Vs = sm + 2 * NTOK * HDIM;
    __shared__ float probs[8][NTOK];
    __shared__ float mbs[NTOK];

    const int bh = blockIdx.x;
    const int b  = bh / HEADS, hh = bh % HEADS;
    const float* base = QKV + (long)b * NTOK * (3 * EMBED) + hh * HDIM;

    for (int idx = threadIdx.x; idx < NTOK * HDIM; idx += 256) {
        const int i = idx >> 6, c = idx & 63;
        const float* p = base + (long)i * (3 * EMBED) + c;
        Qs[idx] = p[0] * 0.125f;
        Ks[idx] = p[EMBED];
        Vs[idx] = p[2 * EMBED];
    }
    if (threadIdx.x < NTOK) mbs[threadIdx.x] = MB[b * NTOK + threadIdx.x];
    __syncthreads();

    const int warp = threadIdx.x >> 5, lane = threadIdx.x & 31;

    for (int i = warp; i < NTOK; i += 8) {
        int nk, fbase = 0;
        if (i == 0) nk = NTOK;
        else { const int f = (i - 1) / LTOK; fbase = 1 + f * LTOK; nk = LTOK + 1; }

        float sims[3];
        float mx = -1e30f;
        int s = 0;
        for (int t = lane; t < nk; t += 32, s++) {
            const int tok = (i == 0) ? t : (t == 0 ? 0 : fbase + t - 1);
            const float* kk = Ks + tok * HDIM;
            const float* qq = Qs + i * HDIM;
            float d = 0.0f;
            #pragma unroll
            for (int c = 0; c < HDIM; c++) d = fmaf(qq[c], kk[c], d);
            sims[s] = d + mbs[tok];
            mx = fmaxf(mx, sims[s]);
        }
        for (int o = 16; o; o >>= 1) mx = fmaxf(mx, __shfl_xor_sync(0xffffffffu, mx, o));
        float lsum = 0.0f;
        s = 0;
        for (int t = lane; t < nk; t += 32, s++) {
            const float p = expf(sims[s] - mx);
            probs[warp][t] = p;
            lsum += p;
        }
        for (int o = 16; o; o >>= 1) lsum += __shfl_xor_sync(0xffffffffu, lsum, o);
        const float inv = 1.0f / lsum;
        __syncwarp();

        float o0 = 0.0f, o1 = 0.0f;
        const int c0 = lane * 2;
        for (int t = 0; t < nk; t++) {
            const int tok = (i == 0) ? t : (t == 0 ? 0 : fbase + t - 1);
            const float p = probs[warp][t];
            o0 = fmaf(p, Vs[tok * HDIM + c0],     o0);
            o1 = fmaf(p, Vs[tok * HDIM + c0 + 1], o1);
        }
        const long oi = ((long)(b * NTOK + i)) * EMBED + hh * HDIM + c0;
        __nv_bfloat16 h, l;
        split2(o0 * inv, h, l); Oh[oi] = h;     Ol[oi] = l;
        split2(o1 * inv, h, l); Oh[oi + 1] = h; Ol[oi + 1] = l;
        __syncwarp();
    }
}

// ---------------- embed epilogue ----------------
__global__ void __launch_bounds__(256) embed_finish_k(
    const float* __restrict__ S, const float* __restrict__ x,
    const float* __restrict__ objb, const float* __restrict__ posb,
    const float* __restrict__ posW, const float* __restrict__ te,
    const int* __restrict__ xmask, float* __restrict__ X, float* __restrict__ MB)
{
    const int t = blockIdx.x;
    const int b = t / (FRAMES * LTOK);
    const int j = t % (FRAMES * LTOK);
    const int f = j / LTOK;

    __shared__ float xp[6];
    if (threadIdx.x < 6) xp[threadIdx.x] = x[(long)t * XROW + FEAT + threadIdx.x];
    __syncthreads();

    const long orow = ((long)b * NTOK + 1 + j) * EMBED;
    for (int e = threadIdx.x; e < EMBED; e += 256) {
        float v = S[(long)t * EMBED + e] + objb[e] + posb[e] + te[f * EMBED + e];
        #pragma unroll
        for (int k = 0; k < 6; k++) v = fmaf(xp[k], posW[e * 6 + k], v);
        X[orow + e] = v;
    }
    if (threadIdx.x == 0) MB[b * NTOK + 1 + j] = xmask[t] ? 0.0f : -100.0f;
}

__global__ void __launch_bounds__(256) cls_init_k(
    const float* __restrict__ cls_tok, const float* __restrict__ cls_pos,
    float* __restrict__ X, float* __restrict__ MB)
{
    const int b = blockIdx.x;
    for (int e = threadIdx.x; e < EMBED; e += 256)
        X[(long)b * NTOK * EMBED + e] = cls_tok[e] + cls_pos[e];
    if (threadIdx.x == 0) MB[b * NTOK] = 0.0f;
}

__global__ void __launch_bounds__(256) copy_mbias_k(
    const float* __restrict__ MB, float* __restrict__ out)
{
    const int i = blockIdx.x * 256 + threadIdx.x;
    if (i < M_ALL) out[i] = MB[i];
}

// ---------------- host orchestration ----------------
#define GEMM_SMEM (STAGES * STAGE_BYTES)   // 98304

extern "C" void kernel_launch(void* const* d_in, const int* in_sizes, int n_in,
                              void* d_out, int out_size)
{
    const float* x        = (const float*)d_in[0];
    const int*   x_mask   = (const int*)  d_in[1];
    const float* obj_W    = (const float*)d_in[2];
    const float* obj_b    = (const float*)d_in[3];
    const float* pos_W    = (const float*)d_in[4];
    const float* pos_b    = (const float*)d_in[5];
    const float* cls_tok  = (const float*)d_in[6];
    const float* cls_pos  = (const float*)d_in[7];
    const float* temporal = (const float*)d_in[8];
    const float* ln1_w    = (const float*)d_in[9];
    const float* ln1_b    = (const float*)d_in[10];
    const float* ln2_w    = (const float*)d_in[11];
    const float* ln2_b    = (const float*)d_in[12];
    const float* qkv_W    = (const float*)d_in[13];
    const float* qkv_b    = (const float*)d_in[14];
    const float* ap_W     = (const float*)d_in[15];
    const float* ap_b     = (const float*)d_in[16];
    const float* fc1_W    = (const float*)d_in[17];
    const float* fc1_b    = (const float*)d_in[18];
    const float* fc2_W    = (const float*)d_in[19];
    const float* fc2_b    = (const float*)d_in[20];
    const float* proj_W   = (const float*)d_in[21];

    float *gX, *gS, *gM;
    __nv_bfloat16 *gAh, *gAl, *gBh, *gBl, *gWh, *gWl;
    cudaGetSymbolAddress((void**)&gX, g_X);
    cudaGetSymbolAddress((void**)&gS, g_S);
    cudaGetSymbolAddress((void**)&gM, g_MB);
    cudaGetSymbolAddress((void**)&gAh, g_Ah);
    cudaGetSymbolAddress((void**)&gAl, g_Al);
    cudaGetSymbolAddress((void**)&gBh, g_Bh);
    cudaGetSymbolAddress((void**)&gBl, g_Bl);
    cudaGetSymbolAddress((void**)&gWh, g_Wh);
    cudaGetSymbolAddress((void**)&gWl, g_Wl);

    const int attn_smem = 3 * NTOK * HDIM * (int)sizeof(float);
    cudaFuncSetAttribute(attn_k, cudaFuncAttributeMaxDynamicSharedMemorySize, attn_smem);
    cudaFuncSetAttribute(gemm_mma<0,0,0>, cudaFuncAttributeMaxDynamicSharedMemorySize, GEMM_SMEM);
    cudaFuncSetAttribute(gemm_mma<0,1,0>, cudaFuncAttributeMaxDynamicSharedMemorySize, GEMM_SMEM);
    cudaFuncSetAttribute(gemm_mma<1,0,1>, cudaFuncAttributeMaxDynamicSharedMemorySize, GEMM_SMEM);

    // ---- weight conversion (once per call) ----
    split_k<<<2048, 256>>>(obj_W,  gWh + OFF_OBJ,  gWl + OFF_OBJ,  (long)EMBED * FEAT);
    split_k<<<2048, 256>>>(qkv_W,  gWh + OFF_QKV,  gWl + OFF_QKV,  (long)DEPTH * 3 * EMBED * EMBED);
    split_k<<<2048, 256>>>(ap_W,   gWh + OFF_AP,   gWl + OFF_AP,   (long)DEPTH * EMBED * EMBED);
    split_k<<<2048, 256>>>(fc1_W,  gWh + OFF_FC1,  gWl + OFF_FC1,  (long)DEPTH * 4 * EMBED * EMBED);
    split_k<<<2048, 256>>>(fc2_W,  gWh + OFF_FC2,  gWl + OFF_FC2,  (long)DEPTH * EMBED * 4 * EMBED);
    split_k<<<2048, 256>>>(proj_W, gWh + OFF_PROJ, gWl + OFF_PROJ, (long)OUTD * EMBED);

    // ---- embedding ----
    split_x_k<<<2048, 256>>>(x, gAh, gAl);
    gemm_mma<0,0,0><<<dim3(EMBED / 128, M_SPAT / 128), 256, GEMM_SMEM>>>(
        gAh, gAl, FEAT, gWh + OFF_OBJ, gWl + OFF_OBJ, FEAT,
        nullptr, gS, nullptr, nullptr, EMBED, FEAT);
    embed_finish_k<<<M_SPAT, 256>>>(gS, x, obj_b, pos_b, pos_W, temporal, x_mask, gX, gM);
    cls_init_k<<<BATCH, 256>>>(cls_tok, cls_pos, gX, gM);

    // ---- layers ----
    for (int l = 0; l < DEPTH; l++) {
        const __nv_bfloat16* qWh = gWh + OFF_QKV + (long)l * 3 * EMBED * EMBED;
        const __nv_bfloat16* qWl = gWl + OFF_QKV + (long)l * 3 * EMBED * EMBED;
        const __nv_bfloat16* aWh = gWh + OFF_AP  + (long)l * EMBED * EMBED;
        const __nv_bfloat16* aWl = gWl + OFF_AP  + (long)l * EMBED * EMBED;
        const __nv_bfloat16* f1h = gWh + OFF_FC1 + (long)l * 4 * EMBED * EMBED;
        const __nv_bfloat16* f1l = gWl + OFF_FC1 + (long)l * 4 * EMBED * EMBED;
        const __nv_bfloat16* f2h = gWh + OFF_FC2 + (long)l * EMBED * 4 * EMBED;
        const __nv_bfloat16* f2l = gWl + OFF_FC2 + (long)l * EMBED * 4 * EMBED;
        const float* qb  = qkv_b + (long)l * 3 * EMBED;
        const float* ab  = ap_b  + (long)l * EMBED;
        const float* f1b = fc1_b + (long)l * 4 * EMBED;
        const float* f2b = fc2_b + (long)l * EMBED;

        ln_k<<<M_ALL, 256>>>(gX, ln1_w + l * EMBED, ln1_b + l * EMBED, gBh, gBl);
        gemm_mma<0,0,0><<<dim3(3 * EMBED / 128, M_ALL / 128), 256, GEMM_SMEM>>>(
            gBh, gBl, EMBED, qWh, qWl, EMBED, qb, gS, nullptr, nullptr, 3 * EMBED, EMBED);
        attn_k<<<BATCH * HEADS, 256, attn_smem>>>(gS, gM, gBh, gBl);
        gemm_mma<0,1,0><<<dim3(EMBED / 128, M_ALL / 128), 256, GEMM_SMEM>>>(
            gBh, gBl, EMBED, aWh, aWl, EMBED, ab, gX, nullptr, nullptr, EMBED, EMBED);
        ln_k<<<M_ALL, 256>>>(gX, ln2_w + l * EMBED, ln2_b + l * EMBED, gBh, gBl);
        gemm_mma<1,0,1><<<dim3(4 * EMBED / 128, M_ALL / 128), 256, GEMM_SMEM>>>(
            gBh, gBl, EMBED, f1h, f1l, EMBED, f1b, nullptr, gAh, gAl, 4 * EMBED, EMBED);
        gemm_mma<0,1,0><<<dim3(EMBED / 128, M_ALL / 128), 256, GEMM_SMEM>>>(
            gAh, gAl, 4 * EMBED, f2h, f2l, 4 * EMBED, f2b, gX, nullptr, nullptr, EMBED, 4 * EMBED);
    }

    // ---- head ----
    float* out = (float*)d_out;
    split_k<<<2048, 256>>>(gX, gBh, gBl, (long)M_ALL * EMBED);
    gemm_mma<0,0,0><<<dim3(OUTD / 128, M_ALL / 128), 256, GEMM_SMEM>>>(
        gBh, gBl, EMBED, gWh + OFF_PROJ, gWl + OFF_PROJ, EMBED,
        nullptr, out, nullptr, nullptr, OUTD, EMBED);

    if (out_size >= M_ALL * OUTD + M_ALL) {
        copy_mbias_k<<<(M_ALL + 255) / 256, 256>>>(gM, out + (long)M_ALL * OUTD);
    }
}

// round 7
// speedup vs baseline: 4.3516x; 1.0042x over previous
#include <cuda_runtime.h>
#include <cuda_bf16.h>
#include <math.h>
#include <stdint.h>

// ---------------- problem constants ----------------
#define BATCH   256
#define FRAMES  4
#define LTOK    20
#define NTOK    81
#define EMBED   768
#define HEADS   12
#define HDIM    64
#define DEPTH   12
#define FEAT    2048
#define XROW    2054
#define M_ALL   (BATCH * NTOK)          // 20736
#define M_SPAT  (BATCH * FRAMES * LTOK) // 20480
#define OUTD    256

// weight offsets (elements) in the packed bf16 weight buffers
#define OFF_OBJ  0L
#define OFF_QKV  1572864L
#define OFF_AP   22806528L
#define OFF_FC1  29884416L
#define OFF_FC2  58195968L
#define OFF_PROJ 86507520L
#define W_TOTAL  86704128L

// ---------------- scratch ----------------
__device__ float g_X[M_ALL * EMBED];
__device__ float g_S[M_ALL * 4 * EMBED];
__device__ float g_MB[M_ALL];
__device__ __nv_bfloat16 g_Ah[63700992];          // M_ALL*3072 (embed input / fc1 out)
__device__ __nv_bfloat16 g_Al[63700992];
__device__ __nv_bfloat16 g_Bh[M_ALL * EMBED];     // 768-wide activations
__device__ __nv_bfloat16 g_Bl[M_ALL * EMBED];
__device__ __nv_bfloat16 g_Wh[W_TOTAL];
__device__ __nv_bfloat16 g_Wl[W_TOTAL];

// ---------------- helpers ----------------
__device__ __forceinline__ uint32_t smem_u32(const void* p) {
    uint32_t a;
    asm("{ .reg .u64 t; cvta.to.shared.u64 t, %1; cvt.u32.u64 %0, t; }" : "=r"(a) : "l"(p));
    return a;
}
__device__ __forceinline__ void cpa16(uint32_t dst, const void* src) {
    asm volatile("cp.async.cg.shared.global [%0], [%1], 16;" :: "r"(dst), "l"(src));
}
__device__ __forceinline__ void ldsm4(uint32_t* r, uint32_t addr) {
    asm volatile("ldmatrix.sync.aligned.m8n8.x4.shared.b16 {%0,%1,%2,%3}, [%4];"
                 : "=r"(r[0]), "=r"(r[1]), "=r"(r[2]), "=r"(r[3]) : "r"(addr));
}
__device__ __forceinline__ void mma16816(float* c, const uint32_t* a, const uint32_t* b) {
    asm volatile(
        "mma.sync.aligned.m16n8k16.row.col.f32.bf16.bf16.f32 "
        "{%0,%1,%2,%3}, {%4,%5,%6,%7}, {%8,%9}, {%0,%1,%2,%3};"
        : "+f"(c[0]), "+f"(c[1]), "+f"(c[2]), "+f"(c[3])
        : "r"(a[0]), "r"(a[1]), "r"(a[2]), "r"(a[3]), "r"(b[0]), "r"(b[1]));
}
__device__ __forceinline__ float gelu_exact(float x) {
    return 0.5f * x * (1.0f + erff(x * 0.70710678118654752f));
}
__device__ __forceinline__ void split2(float v, __nv_bfloat16& h, __nv_bfloat16& l) {
    h = __float2bfloat16(v);
    l = __float2bfloat16(v - __bfloat162float(h));
}

// KC=32 tile layout: logical 128 rows x 32 cols bf16 (64B/row) packed as
// 64 physical rows x 128B.  addr(r, g) = (r>>1)*128 + ((( ((r&1)<<2) | g ) ^ ((r>>1)&7)) << 4)
__device__ __forceinline__ uint32_t tile_off(int r, int g) {
    const int p = r >> 1;
    const int x = ((((r & 1) << 2) | g) ^ (p & 7));
    return (uint32_t)((p << 7) + (x << 4));
}

// ---------------- bf16 hi/lo split GEMM, KC=32, 3 stages, 2 CTA/SM, 1 sync/chunk ----
#define KC 32
#define STAGES 3
#define STAGE_BYTES 32768  // 4 buffers x 8KB

template<int ACT, int ACC, int OSPLIT>
__global__ void __launch_bounds__(256, 2) gemm_mma(
    const __nv_bfloat16* __restrict__ Ah, const __nv_bfloat16* __restrict__ Al, int lda,
    const __nv_bfloat16* __restrict__ Bh, const __nv_bfloat16* __restrict__ Bl, int ldw,
    const float* __restrict__ bias,
    float* __restrict__ C,
    __nv_bfloat16* __restrict__ Oh, __nv_bfloat16* __restrict__ Ol,
    int ldc, int K)
{
    extern __shared__ char smem[];
    const uint32_t sbase = smem_u32(smem);
    const int tid = threadIdx.x, wid = tid >> 5, lane = tid & 31;
    const int row0 = blockIdx.y * 128, col0 = blockIdx.x * 128;
    const int warp_m = (wid & 1) * 64, warp_n = (wid >> 1) * 32;

    const __nv_bfloat16* g0 = Ah + (long)row0 * lda;
    const __nv_bfloat16* g1 = Al + (long)row0 * lda;
    const __nv_bfloat16* g2 = Bh + (long)col0 * ldw;
    const __nv_bfloat16* g3 = Bl + (long)col0 * ldw;

    float acc[4][4][4];
    #pragma unroll
    for (int a = 0; a < 4; a++)
        #pragma unroll
        for (int b = 0; b < 4; b++)
            #pragma unroll
            for (int c = 0; c < 4; c++) acc[a][b][c] = 0.0f;

    const int id  = lane >> 3;
    const int rin = lane & 7;
    const int a_row = warp_m + ((id & 1) << 3) + rin;
    const int b_row = warp_n + ((id >> 1) << 3) + rin;
    const int ag = id >> 1;
    const int bg = id & 1;

    const int l_row0 = tid >> 2,          l_g0 = tid & 3;
    const int l_row1 = (tid + 256) >> 2,  l_g1 = tid & 3;
    const uint32_t l_off0 = tile_off(l_row0, l_g0);
    const uint32_t l_off1 = tile_off(l_row1, l_g1);

    const int nk = K / KC;

#define LOAD_STAGE(stage, k0)                                                        \
    {                                                                                \
        const uint32_t st_ = sbase + (stage) * STAGE_BYTES;                          \
        cpa16(st_ + l_off0,          g0 + (long)l_row0 * lda + (k0) + l_g0 * 8);     \
        cpa16(st_ + l_off1,          g0 + (long)l_row1 * lda + (k0) + l_g1 * 8);     \
        cpa16(st_ + 8192  + l_off0,  g1 + (long)l_row0 * lda + (k0) + l_g0 * 8);     \
        cpa16(st_ + 8192  + l_off1,  g1 + (long)l_row1 * lda + (k0) + l_g1 * 8);     \
        cpa16(st_ + 16384 + l_off0,  g2 + (long)l_row0 * ldw + (k0) + l_g0 * 8);     \
        cpa16(st_ + 16384 + l_off1,  g2 + (long)l_row1 * ldw + (k0) + l_g1 * 8);     \
        cpa16(st_ + 24576 + l_off0,  g3 + (long)l_row0 * ldw + (k0) + l_g0 * 8);     \
        cpa16(st_ + 24576 + l_off1,  g3 + (long)l_row1 * ldw + (k0) + l_g1 * 8);     \
        asm volatile("cp.async.commit_group;" ::: "memory");                         \
    }

    LOAD_STAGE(0, 0);
    if (nk > 1) LOAD_STAGE(1, KC);

    for (int ck = 0; ck < nk; ck++) {
        // stage ck ready once pending groups <= 1 ({ck, ck+1} are in flight)
        if (ck + 1 < nk) {
            asm volatile("cp.async.wait_group 1;" ::: "memory");
        } else {
            asm volatile("cp.async.wait_group 0;" ::: "memory");
        }
        __syncthreads();
        // safe to overwrite stage (ck+2)%3: it was read at ck-1, and every warp
        // finished ck-1's compute before arriving at the sync above.
        if (ck + 2 < nk) LOAD_STAGE((ck + 2) % STAGES, (ck + 2) * KC);

        const uint32_t st = sbase + (ck % STAGES) * STAGE_BYTES;
        const uint32_t sAh_ = st, sAl_ = st + 8192, sBh_ = st + 16384, sBl_ = st + 24576;

        #pragma unroll
        for (int ks = 0; ks < 2; ks++) {
            uint32_t bh[2][4], bl[2][4];
            #pragma unroll
            for (int ntp = 0; ntp < 2; ntp++) {
                const uint32_t off = tile_off(b_row + ntp * 16, 2 * ks + bg);
                ldsm4(bh[ntp], sBh_ + off);
                ldsm4(bl[ntp], sBl_ + off);
            }
            #pragma unroll
            for (int mt = 0; mt < 4; mt++) {
                const uint32_t off = tile_off(a_row + mt * 16, 2 * ks + ag);
                uint32_t ah[4], al[4];
                ldsm4(ah, sAh_ + off);
                ldsm4(al, sAl_ + off);
                #pragma unroll
                for (int nt = 0; nt < 4; nt++) {
                    uint32_t* fh = &bh[nt >> 1][(nt & 1) * 2];
                    uint32_t* fl = &bl[nt >> 1][(nt & 1) * 2];
                    mma16816(acc[mt][nt], ah, fh);
                    mma16816(acc[mt][nt], ah, fl);
                    mma16816(acc[mt][nt], al, fh);
                }
            }
        }
    }
#undef LOAD_STAGE

    #pragma unroll
    for (int mt = 0; mt < 4; mt++) {
        #pragma unroll
        for (int nt = 0; nt < 4; nt++) {
            const int r = row0 + warp_m + mt * 16 + (lane >> 2);
            const int c = col0 + warp_n + nt * 8 + (lane & 3) * 2;
            const float b0 = bias ? bias[c] : 0.0f;
            const float b1 = bias ? bias[c + 1] : 0.0f;
            #pragma unroll
            for (int h = 0; h < 2; h++) {
                const long rr = r + h * 8;
                float v0 = acc[mt][nt][h * 2 + 0] + b0;
                float v1 = acc[mt][nt][h * 2 + 1] + b1;
                if (ACT) { v0 = gelu_exact(v0); v1 = gelu_exact(v1); }
                if (ACC) {
                    float2 old = *(const float2*)&C[rr * ldc + c];
                    v0 += old.x; v1 += old.y;
                    float2 nv = {v0, v1};
                    *(float2*)&C[rr * ldc + c] = nv;
                } else if (OSPLIT) {
                    __nv_bfloat16 h0, l0, h1, l1;
                    split2(v0, h0, l0);
                    split2(v1, h1, l1);
                    __nv_bfloat162 hv = {h0, h1}, lv = {l0, l1};
                    *(__nv_bfloat162*)&Oh[rr * ldc + c] = hv;
                    *(__nv_bfloat162*)&Ol[rr * ldc + c] = lv;
                } else {
                    float2 nv = {v0, v1};
                    *(float2*)&C[rr * ldc + c] = nv;
                }
            }
        }
    }
}

// ---------------- fp32 -> (hi, lo) bf16 split ----------------
__global__ void __launch_bounds__(256) split_k(
    const float* __restrict__ in, __nv_bfloat16* __restrict__ hi,
    __nv_bfloat16* __restrict__ lo, long n)
{
    for (long i = blockIdx.x * 256L + threadIdx.x; i < n; i += gridDim.x * 256L) {
        const float v = in[i];
        __nv_bfloat16 h, l;
        split2(v, h, l);
        hi[i] = h; lo[i] = l;
    }
}
__global__ void __launch_bounds__(256) split_x_k(
    const float* __restrict__ in, __nv_bfloat16* __restrict__ hi,
    __nv_bfloat16* __restrict__ lo)
{
    const long n = (long)M_SPAT * FEAT;
    for (long i = blockIdx.x * 256L + threadIdx.x; i < n; i += gridDim.x * 256L) {
        const long r = i >> 11, c = i & 2047;
        const float v = in[r * XROW + c];
        __nv_bfloat16 h, l;
        split2(v, h, l);
        hi[i] = h; lo[i] = l;
    }
}

// ---------------- LayerNorm -> hi/lo bf16 ----------------
__global__ void __launch_bounds__(256) ln_k(
    const float* __restrict__ X, const float* __restrict__ w,
    const float* __restrict__ b, __nv_bfloat16* __restrict__ Yh,
    __nv_bfloat16* __restrict__ Yl)
{
    const long t = blockIdx.x;
    const float* xr = X + t * EMBED;
    const int tid = threadIdx.x;

    float v0 = xr[tid], v1 = xr[tid + 256], v2 = xr[tid + 512];
    float s  = v0 + v1 + v2;
    float ss = v0 * v0 + v1 * v1 + v2 * v2;

    __shared__ float red[16];
    for (int o = 16; o; o >>= 1) {
        s  += __shfl_xor_sync(0xffffffffu, s,  o);
        ss += __shfl_xor_sync(0xffffffffu, ss, o);
    }
    const int warp = tid >> 5, lane = tid & 31;
    if (lane == 0) { red[warp] = s; red[warp + 8] = ss; }
    __syncthreads();
    __shared__ float smean, srstd;
    if (tid == 0) {
        float S = 0, SS = 0;
        #pragma unroll
        for (int i = 0; i < 8; i++) { S += red[i]; SS += red[i + 8]; }
        float m   = S * (1.0f / EMBED);
        float var = SS * (1.0f / EMBED) - m * m;
        smean = m;
        srstd = rsqrtf(var + 1e-6f);
    }
    __syncthreads();
    const float m = smean, r = srstd;
    __nv_bfloat16 h, l;
    float y;
    y = (v0 - m) * r * w[tid] + b[tid];
    split2(y, h, l); Yh[t * EMBED + tid] = h; Yl[t * EMBED + tid] = l;
    y = (v1 - m) * r * w[tid + 256] + b[tid + 256];
    split2(y, h, l); Yh[t * EMBED + tid + 256] = h; Yl[t * EMBED + tid + 256] = l;
    y = (v2 - m) * r * w[tid + 512] + b[tid + 512];
    split2(y, h, l); Yh[t * EMBED + tid + 512] = h; Yl[t * EMBED + tid + 512] = l;
}

// ---------------- attention -> hi/lo bf16 output ----------------
__global__ void __launch_bounds__(256) attn_k(
    const float* __restrict__ QKV, const float* __restrict__ MB,
    __nv_bfloat16* __restrict__ Oh, __nv_bfloat16* __restrict__ Ol)
{
    extern __shared__ float sm[];
    float* Qs = sm;
    float* Ks = sm + NTOK * HDIM;
    float* Vs = sm + 2 * NTOK * HDIM;
    __shared__ float probs[8][NTOK];
    __shared__ float mbs[NTOK];

    const int bh = blockIdx.x;
    const int b  = bh / HEADS, hh = bh % HEADS;
    const float* base = QKV + (long)b * NTOK * (3 * EMBED) + hh * HDIM;

    for (int idx = threadIdx.x; idx < NTOK * HDIM; idx += 256) {
        const int i = idx >> 6, c = idx & 63;
        const float* p = base + (long)i * (3 * EMBED) + c;
        Qs[idx] = p[0] * 0.125f;
        Ks[idx] = p[EMBED];
        Vs[idx] = p[2 * EMBED];
    }
    if (threadIdx.x < NTOK) mbs[threadIdx.x] = MB[b * NTOK + threadIdx.x];
    __syncthreads();

    const int warp = threadIdx.x >> 5, lane = threadIdx.x & 31;

    for (int i = warp; i < NTOK; i += 8) {
        int nk, fbase = 0;
        if (i == 0) nk = NTOK;
        else { const int f = (i - 1) / LTOK; fbase = 1 + f * LTOK; nk = LTOK + 1; }

        float sims[3];
        float mx = -1e30f;
        int s = 0;
        for (int t = lane; t < nk; t += 32, s++) {
            const int tok = (i == 0) ? t : (t == 0 ? 0 : fbase + t - 1);
            const float* kk = Ks + tok * HDIM;
            const float* qq = Qs + i * HDIM;
            float d = 0.0f;
            #pragma unroll
            for (int c = 0; c < HDIM; c++) d = fmaf(qq[c], kk[c], d);
            sims[s] = d + mbs[tok];
            mx = fmaxf(mx, sims[s]);
        }
        for (int o = 16; o; o >>= 1) mx = fmaxf(mx, __shfl_xor_sync(0xffffffffu, mx, o));
        float lsum = 0.0f;
        s = 0;
        for (int t = lane; t < nk; t += 32, s++) {
            const float p = expf(sims[s] - mx);
            probs[warp][t] = p;
            lsum += p;
        }
        for (int o = 16; o; o >>= 1) lsum += __shfl_xor_sync(0xffffffffu, lsum, o);
        const float inv = 1.0f / lsum;
        __syncwarp();

        float o0 = 0.0f, o1 = 0.0f;
        const int c0 = lane * 2;
        for (int t = 0; t < nk; t++) {
            const int tok = (i == 0) ? t : (t == 0 ? 0 : fbase + t - 1);
            const float p = probs[warp][t];
            o0 = fmaf(p, Vs[tok * HDIM + c0],     o0);
            o1 = fmaf(p, Vs[tok * HDIM + c0 + 1], o1);
        }
        const long oi = ((long)(b * NTOK + i)) * EMBED + hh * HDIM + c0;
        __nv_bfloat16 h, l;
        split2(o0 * inv, h, l); Oh[oi] = h;     Ol[oi] = l;
        split2(o1 * inv, h, l); Oh[oi + 1] = h; Ol[oi + 1] = l;
        __syncwarp();
    }
}

// ---------------- embed epilogue ----------------
__global__ void __launch_bounds__(256) embed_finish_k(
    const float* __restrict__ S, const float* __restrict__ x,
    const float* __restrict__ objb, const float* __restrict__ posb,
    const float* __restrict__ posW, const float* __restrict__ te,
    const int* __restrict__ xmask, float* __restrict__ X, float* __restrict__ MB)
{
    const int t = blockIdx.x;
    const int b = t / (FRAMES * LTOK);
    const int j = t % (FRAMES * LTOK);
    const int f = j / LTOK;

    __shared__ float xp[6];
    if (threadIdx.x < 6) xp[threadIdx.x] = x[(long)t * XROW + FEAT + threadIdx.x];
    __syncthreads();

    const long orow = ((long)b * NTOK + 1 + j) * EMBED;
    for (int e = threadIdx.x; e < EMBED; e += 256) {
        float v = S[(long)t * EMBED + e] + objb[e] + posb[e] + te[f * EMBED + e];
        #pragma unroll
        for (int k = 0; k < 6; k++) v = fmaf(xp[k], posW[e * 6 + k], v);
        X[orow + e] = v;
    }
    if (threadIdx.x == 0) MB[b * NTOK + 1 + j] = xmask[t] ? 0.0f : -100.0f;
}

__global__ void __launch_bounds__(256) cls_init_k(
    const float* __restrict__ cls_tok, const float* __restrict__ cls_pos,
    float* __restrict__ X, float* __restrict__ MB)
{
    const int b = blockIdx.x;
    for (int e = threadIdx.x; e < EMBED; e += 256)
        X[(long)b * NTOK * EMBED + e] = cls_tok[e] + cls_pos[e];
    if (threadIdx.x == 0) MB[b * NTOK] = 0.0f;
}

__global__ void __launch_bounds__(256) copy_mbias_k(
    const float* __restrict__ MB, float* __restrict__ out)
{
    const int i = blockIdx.x * 256 + threadIdx.x;
    if (i < M_ALL) out[i] = MB[i];
}

// ---------------- host orchestration ----------------
#define GEMM_SMEM (STAGES * STAGE_BYTES)   // 98304

extern "C" void kernel_launch(void* const* d_in, const int* in_sizes, int n_in,
                              void* d_out, int out_size)
{
    const float* x        = (const float*)d_in[0];
    const int*   x_mask   = (const int*)  d_in[1];
    const float* obj_W    = (const float*)d_in[2];
    const float* obj_b    = (const float*)d_in[3];
    const float* pos_W    = (const float*)d_in[4];
    const float* pos_b    = (const float*)d_in[5];
    const float* cls_tok  = (const float*)d_in[6];
    const float* cls_pos  = (const float*)d_in[7];
    const float* temporal = (const float*)d_in[8];
    const float* ln1_w    = (const float*)d_in[9];
    const float* ln1_b    = (const float*)d_in[10];
    const float* ln2_w    = (const float*)d_in[11];
    const float* ln2_b    = (const float*)d_in[12];
    const float* qkv_W    = (const float*)d_in[13];
    const float* qkv_b    = (const float*)d_in[14];
    const float* ap_W     = (const float*)d_in[15];
    const float* ap_b     = (const float*)d_in[16];
    const float* fc1_W    = (const float*)d_in[17];
    const float* fc1_b    = (const float*)d_in[18];
    const float* fc2_W    = (const float*)d_in[19];
    const float* fc2_b    = (const float*)d_in[20];
    const float* proj_W   = (const float*)d_in[21];

    float *gX, *gS, *gM;
    __nv_bfloat16 *gAh, *gAl, *gBh, *gBl, *gWh, *gWl;
    cudaGetSymbolAddress((void**)&gX, g_X);
    cudaGetSymbolAddress((void**)&gS, g_S);
    cudaGetSymbolAddress((void**)&gM, g_MB);
    cudaGetSymbolAddress((void**)&gAh, g_Ah);
    cudaGetSymbolAddress((void**)&gAl, g_Al);
    cudaGetSymbolAddress((void**)&gBh, g_Bh);
    cudaGetSymbolAddress((void**)&gBl, g_Bl);
    cudaGetSymbolAddress((void**)&gWh, g_Wh);
    cudaGetSymbolAddress((void**)&gWl, g_Wl);

    const int attn_smem = 3 * NTOK * HDIM * (int)sizeof(float);
    cudaFuncSetAttribute(attn_k, cudaFuncAttributeMaxDynamicSharedMemorySize, attn_smem);
    cudaFuncSetAttribute(gemm_mma<0,0,0>, cudaFuncAttributeMaxDynamicSharedMemorySize, GEMM_SMEM);
    cudaFuncSetAttribute(gemm_mma<0,1,0>, cudaFuncAttributeMaxDynamicSharedMemorySize, GEMM_SMEM);
    cudaFuncSetAttribute(gemm_mma<1,0,1>, cudaFuncAttributeMaxDynamicSharedMemorySize, GEMM_SMEM);

    // ---- launch order chosen so launch #6 is the embed gemm (ncu -s 5 -c 1) ----
    split_x_k<<<2048, 256>>>(x, gAh, gAl);                                             // 1
    split_k<<<2048, 256>>>(obj_W,  gWh + OFF_OBJ,  gWl + OFF_OBJ,  (long)EMBED * FEAT);// 2
    split_k<<<2048, 256>>>(qkv_W,  gWh + OFF_QKV,  gWl + OFF_QKV,  (long)DEPTH * 3 * EMBED * EMBED); // 3
    split_k<<<2048, 256>>>(ap_W,   gWh + OFF_AP,   gWl + OFF_AP,   (long)DEPTH * EMBED * EMBED);     // 4
    split_k<<<2048, 256>>>(fc1_W,  gWh + OFF_FC1,  gWl + OFF_FC1,  (long)DEPTH * 4 * EMBED * EMBED); // 5
    gemm_mma<0,0,0><<<dim3(EMBED / 128, M_SPAT / 128), 256, GEMM_SMEM>>>(              // 6  <- profiled
        gAh, gAl, FEAT, gWh + OFF_OBJ, gWl + OFF_OBJ, FEAT,
        nullptr, gS, nullptr, nullptr, EMBED, FEAT);
    split_k<<<2048, 256>>>(fc2_W,  gWh + OFF_FC2,  gWl + OFF_FC2,  (long)DEPTH * EMBED * 4 * EMBED);
    split_k<<<2048, 256>>>(proj_W, gWh + OFF_PROJ, gWl + OFF_PROJ, (long)OUTD * EMBED);
    embed_finish_k<<<M_SPAT, 256>>>(gS, x, obj_b, pos_b, pos_W, temporal, x_mask, gX, gM);
    cls_init_k<<<BATCH, 256>>>(cls_tok, cls_pos, gX, gM);

    // ---- layers ----
    for (int l = 0; l < DEPTH; l++) {
        const __nv_bfloat16* qWh = gWh + OFF_QKV + (long)l * 3 * EMBED * EMBED;
        const __nv_bfloat16* qWl = gWl + OFF_QKV + (long)l * 3 * EMBED * EMBED;
        const __nv_bfloat16* aWh = gWh + OFF_AP  + (long)l * EMBED * EMBED;
        const __nv_bfloat16* aWl = gWl + OFF_AP  + (long)l * EMBED * EMBED;
        const __nv_bfloat16* f1h = gWh + OFF_FC1 + (long)l * 4 * EMBED * EMBED;
        const __nv_bfloat16* f1l = gWl + OFF_FC1 + (long)l * 4 * EMBED * EMBED;
        const __nv_bfloat16* f2h = gWh + OFF_FC2 + (long)l * EMBED * 4 * EMBED;
        const __nv_bfloat16* f2l = gWl + OFF_FC2 + (long)l * EMBED * 4 * EMBED;
        const float* qb  = qkv_b + (long)l * 3 * EMBED;
        const float* ab  = ap_b  + (long)l * EMBED;
        const float* f1b = fc1_b + (long)l * 4 * EMBED;
        const float* f2b = fc2_b + (long)l * EMBED;

        ln_k<<<M_ALL, 256>>>(gX, ln1_w + l * EMBED, ln1_b + l * EMBED, gBh, gBl);
        gemm_mma<0,0,0><<<dim3(3 * EMBED / 128, M_ALL / 128), 256, GEMM_SMEM>>>(
            gBh, gBl, EMBED, qWh, qWl, EMBED, qb, gS, nullptr, nullptr, 3 * EMBED, EMBED);
        attn_k<<<BATCH * HEADS, 256, attn_smem>>>(gS, gM, gBh, gBl);
        gemm_mma<0,1,0><<<dim3(EMBED / 128, M_ALL / 128), 256, GEMM_SMEM>>>(
            gBh, gBl, EMBED, aWh, aWl, EMBED, ab, gX, nullptr, nullptr, EMBED, EMBED);
        ln_k<<<M_ALL, 256>>>(gX, ln2_w + l * EMBED, ln2_b + l * EMBED, gBh, gBl);
        gemm_mma<1,0,1><<<dim3(4 * EMBED / 128, M_ALL / 128), 256, GEMM_SMEM>>>(
            gBh, gBl, EMBED, f1h, f1l, EMBED, f1b, nullptr, gAh, gAl, 4 * EMBED, EMBED);
        gemm_mma<0,1,0><<<dim3(EMBED / 128, M_ALL / 128), 256, GEMM_SMEM>>>(
            gAh, gAl, 4 * EMBED, f2h, f2l, 4 * EMBED, f2b, gX, nullptr, nullptr, EMBED, 4 * EMBED);
    }

    // ---- head ----
    float* out = (float*)d_out;
    split_k<<<2048, 256>>>(gX, gBh, gBl, (long)M_ALL * EMBED);
    gemm_mma<0,0,0><<<dim3(OUTD / 128, M_ALL / 128), 256, GEMM_SMEM>>>(
        gBh, gBl, EMBED, gWh + OFF_PROJ, gWl + OFF_PROJ, EMBED,
        nullptr, out, nullptr, nullptr, OUTD, EMBED);

    if (out_size >= M_ALL * OUTD + M_ALL) {
        copy_mbias_k<<<(M_ALL + 255) / 256, 256>>>(gM, out + (long)M_ALL * OUTD);
    }
}